// round 3
// baseline (speedup 1.0000x reference)
#include <cuda_runtime.h>
#include <cuda_bf16.h>
#include <math.h>

// Problem constants
#define B    4
#define N1   2048
#define N2   2048
#define NC   4096           // N1+N2
#define D    256
#define HP   64
#define HA   64
#define KNN  16
#define MROW (B*N1*KNN)     // 131072
#define BNQ  (B*N1)         // 8192

// ---------------- scratch (device globals; no allocation allowed) -------------
__device__ float g_dx  [B*N1*D];
__device__ float g_ex  [B*N2*D];
__device__ float g_sx  [B*N1*D];
__device__ float g_spc [B*N1*3];
__device__ int   g_fidx[B*N1];
__device__ float g_q   [B*N1*D];
__device__ float g_k   [B*N1*D];
__device__ float g_v   [B*N1*D];
__device__ int   g_nidx[B*N1*KNN];
__device__ float g_hpos [MROW*HP];
__device__ float g_pos  [MROW*D];
__device__ float g_hattn[MROW*HA];
__device__ float g_attn [MROW*D];
__device__ float g_x   [B*N1*D];
// [0:64) psum [64:128) psq [128:192) asum [192:256) asq
// [256:320) pscale [320:384) pshift [384:448) ascale [448:512) ashift
__device__ float g_stats[512];

// ---------------- FPS: one block per batch, 1024 threads ----------------------
__global__ void fps_kernel(const float* __restrict__ decpc,
                           const float* __restrict__ encpc)
{
    extern __shared__ float sm[];
    float* sx = sm;
    float* sy = sm + NC;
    float* sz = sm + 2*NC;
    __shared__ float swv[32];
    __shared__ int   swi[32];
    __shared__ int   s_last;

    int b = blockIdx.x;
    int tid = threadIdx.x;

    for (int j = tid; j < N1; j += 1024) {
        sx[j] = decpc[((size_t)b*N1 + j)*3 + 0];
        sy[j] = decpc[((size_t)b*N1 + j)*3 + 1];
        sz[j] = decpc[((size_t)b*N1 + j)*3 + 2];
        sx[N1+j] = encpc[((size_t)b*N2 + j)*3 + 0];
        sy[N1+j] = encpc[((size_t)b*N2 + j)*3 + 1];
        sz[N1+j] = encpc[((size_t)b*N2 + j)*3 + 2];
    }
    float md[4];
#pragma unroll
    for (int t = 0; t < 4; t++) md[t] = 1e10f;
    if (tid == 0) { g_fidx[b*N1] = 0; s_last = 0; }
    __syncthreads();

    for (int i = 1; i < N1; i++) {
        int last = s_last;
        float lx = sx[last], ly = sy[last], lz = sz[last];
        float bestv = -1.0f; int besti = 0x7fffffff;
#pragma unroll
        for (int t = 0; t < 4; t++) {
            int j = tid + t*1024;
            float ddx = sx[j]-lx, ddy = sy[j]-ly, ddz = sz[j]-lz;
            float d = ddx*ddx + ddy*ddy + ddz*ddz;
            float mm = fminf(md[t], d);
            md[t] = mm;
            if (mm > bestv) { bestv = mm; besti = j; }
        }
#pragma unroll
        for (int off = 16; off > 0; off >>= 1) {
            float ov = __shfl_down_sync(0xffffffffu, bestv, off);
            int   oi = __shfl_down_sync(0xffffffffu, besti, off);
            if (ov > bestv || (ov == bestv && oi < besti)) { bestv = ov; besti = oi; }
        }
        if ((tid & 31) == 0) { swv[tid>>5] = bestv; swi[tid>>5] = besti; }
        __syncthreads();
        if (tid < 32) {
            bestv = swv[tid]; besti = swi[tid];
#pragma unroll
            for (int off = 16; off > 0; off >>= 1) {
                float ov = __shfl_down_sync(0xffffffffu, bestv, off);
                int   oi = __shfl_down_sync(0xffffffffu, besti, off);
                if (ov > bestv || (ov == bestv && oi < besti)) { bestv = ov; besti = oi; }
            }
            if (tid == 0) { g_fidx[b*N1 + i] = besti; s_last = besti; }
        }
        __syncthreads();
    }
}

// ---------------- gather sampled features + coords ----------------------------
__global__ void gather_kernel(const float* __restrict__ decpc,
                              const float* __restrict__ encpc)
{
    int row = blockIdx.x;              // 0..8191
    int b = row >> 11;
    int j = g_fidx[row];
    const float* src = (j < N1) ? &g_dx[((size_t)b*N1 + j)*D]
                                : &g_ex[((size_t)b*N2 + (j - N1))*D];
    g_sx[(size_t)row*D + threadIdx.x] = src[threadIdx.x];
    if (threadIdx.x < 3) {
        const float* ps = (j < N1) ? &decpc[((size_t)b*N1 + j)*3]
                                   : &encpc[((size_t)b*N2 + (j - N1))*3];
        g_spc[(size_t)row*3 + threadIdx.x] = ps[threadIdx.x];
    }
}

// ---------------- KNN: one thread per query -----------------------------------
__global__ void knn_kernel(const float* __restrict__ decpc)
{
    __shared__ float px[N1], py[N1], pz[N1], s2s[N1];
    int b = blockIdx.y;
    int tid = threadIdx.x;
    for (int m = tid; m < N1; m += 256) {
        float x = g_spc[((size_t)b*N1 + m)*3 + 0];
        float y = g_spc[((size_t)b*N1 + m)*3 + 1];
        float z = g_spc[((size_t)b*N1 + m)*3 + 2];
        px[m] = x; py[m] = y; pz[m] = z;
        s2s[m] = x*x + y*y + z*z;
    }
    __syncthreads();
    int q = blockIdx.x*256 + tid;
    float qx = decpc[((size_t)b*N1 + q)*3 + 0];
    float qy = decpc[((size_t)b*N1 + q)*3 + 1];
    float qz = decpc[((size_t)b*N1 + q)*3 + 2];
    float s1 = qx*qx + qy*qy + qz*qz;
    float bd[KNN]; int bi[KNN];
#pragma unroll
    for (int t = 0; t < KNN; t++) { bd[t] = 1e30f; bi[t] = 0; }
    for (int m = 0; m < N1; m++) {
        float d = s1 + s2s[m] - 2.0f*(qx*px[m] + qy*py[m] + qz*pz[m]);
        if (d < bd[KNN-1]) {
            bd[KNN-1] = d; bi[KNN-1] = m;
#pragma unroll
            for (int t = KNN-1; t > 0; t--) {
                if (bd[t] < bd[t-1]) {
                    float td = bd[t]; bd[t] = bd[t-1]; bd[t-1] = td;
                    int   ti = bi[t]; bi[t] = bi[t-1]; bi[t-1] = ti;
                }
            }
        }
    }
#pragma unroll
    for (int t = 0; t < KNN; t++)
        g_nidx[((size_t)b*N1 + q)*KNN + t] = bi[t];
}

// ---------------- hpos: pos_in @ Wp1 + bp1 ------------------------------------
__global__ void hpos_kernel(const float* __restrict__ decpc,
                            const float* __restrict__ Wp1,
                            const float* __restrict__ bp1)
{
    int m = blockIdx.x*4 + (threadIdx.x >> 6);
    int c = threadIdx.x & 63;
    int b = m >> 15;
    int n = (m >> 4) & 2047;
    int j = g_nidx[m];
    const float* pp = &g_spc[((size_t)b*N1 + j)*3];
    const float* qq = &decpc[((size_t)b*N1 + n)*3];
    float p0 = pp[0]-qq[0], p1 = pp[1]-qq[1], p2 = pp[2]-qq[2];
    float h = p0*Wp1[c] + p1*Wp1[64+c] + p2*Wp1[128+c] + bp1[c];
    g_hpos[(size_t)m*HP + c] = h;
}

// ---------------- column stats over [M,64] matrix ------------------------------
__global__ void colstats_kernel(const float* __restrict__ X, int M,
                                float* __restrict__ sum, float* __restrict__ sumsq)
{
    int c  = threadIdx.x & 63;
    int rg = threadIdx.x >> 6;
    float s = 0.f, s2 = 0.f;
    for (int r = blockIdx.x*4 + rg; r < M; r += gridDim.x*4) {
        float v = X[(size_t)r*64 + c];
        s += v; s2 += v*v;
    }
    __shared__ float sh[256], sh2[256];
    sh[threadIdx.x] = s; sh2[threadIdx.x] = s2;
    __syncthreads();
    if (rg == 0) {
        s  = sh[c]  + sh[64+c]  + sh[128+c]  + sh[192+c];
        s2 = sh2[c] + sh2[64+c] + sh2[128+c] + sh2[192+c];
        atomicAdd(&sum[c], s);
        atomicAdd(&sumsq[c], s2);
    }
}

__global__ void zero_stats_kernel() { g_stats[threadIdx.x] = 0.0f; }

__global__ void finalize_bn_kernel(const float* __restrict__ sum,
                                   const float* __restrict__ sumsq,
                                   const float* __restrict__ g,
                                   const float* __restrict__ beta,
                                   float invM,
                                   float* __restrict__ scale,
                                   float* __restrict__ shift)
{
    int c = threadIdx.x;
    float mean = sum[c]*invM;
    float var  = sumsq[c]*invM - mean*mean;
    float sc = g[c]*rsqrtf(var + 1e-5f);
    scale[c] = sc;
    shift[c] = beta[c] - mean*sc;
}

// ---------------- generic tiled GEMM: C = A@W + bias (+resid) ------------------
#define TBM 64
#define TBN 64
#define TBK 16

__global__ void gemm_bias_kernel(const float* __restrict__ A,
                                 const float* __restrict__ W,
                                 const float* __restrict__ bias,
                                 const float* __restrict__ resid,
                                 float* __restrict__ C,
                                 int M, int N, int K)
{
    __shared__ float As[TBK][TBM];
    __shared__ float Bs[TBK][TBN];
    int tid = threadIdx.x;
    int row0 = blockIdx.y * TBM;
    int col0 = blockIdx.x * TBN;
    int tx = tid & 15, ty = tid >> 4;
    float acc[4][4] = {};
    for (int k0 = 0; k0 < K; k0 += TBK) {
#pragma unroll
        for (int i = 0; i < 4; i++) {
            int idx = tid + i*256;
            int r = idx / TBK, c = idx % TBK;
            As[c][r] = A[(size_t)(row0 + r)*K + k0 + c];
        }
#pragma unroll
        for (int i = 0; i < 4; i++) {
            int idx = tid + i*256;
            int r = idx / TBN, c = idx % TBN;
            Bs[r][c] = W[(size_t)(k0 + r)*N + col0 + c];
        }
        __syncthreads();
#pragma unroll
        for (int kk = 0; kk < TBK; kk++) {
            float a[4], bb[4];
#pragma unroll
            for (int i = 0; i < 4; i++) a[i] = As[kk][ty*4+i];
#pragma unroll
            for (int j = 0; j < 4; j++) bb[j] = Bs[kk][tx*4+j];
#pragma unroll
            for (int i = 0; i < 4; i++)
#pragma unroll
                for (int j = 0; j < 4; j++)
                    acc[i][j] += a[i]*bb[j];
        }
        __syncthreads();
    }
#pragma unroll
    for (int i = 0; i < 4; i++) {
        size_t r = row0 + ty*4 + i;
#pragma unroll
        for (int j = 0; j < 4; j++) {
            int c = col0 + tx*4 + j;
            float v = acc[i][j] + bias[c];
            if (resid) v += resid[r*(size_t)N + c];
            C[r*(size_t)N + c] = v;
        }
    }
}

// ---------------- GEMM with BN+ReLU on A: C = relu(A*sc+sh)@W + bias ----------
__global__ void gemm_bnrelu_kernel(const float* __restrict__ A,
                                   const float* __restrict__ W,
                                   const float* __restrict__ bias,
                                   const float* __restrict__ scale,
                                   const float* __restrict__ shift,
                                   float* __restrict__ C,
                                   int M, int N, int K)
{
    __shared__ float As[TBK][TBM];
    __shared__ float Bs[TBK][TBN];
    int tid = threadIdx.x;
    int row0 = blockIdx.y * TBM;
    int col0 = blockIdx.x * TBN;
    int tx = tid & 15, ty = tid >> 4;
    float acc[4][4] = {};
    for (int k0 = 0; k0 < K; k0 += TBK) {
#pragma unroll
        for (int i = 0; i < 4; i++) {
            int idx = tid + i*256;
            int r = idx / TBK, c = idx % TBK;
            int ch = k0 + c;
            float v = A[(size_t)(row0 + r)*K + ch];
            v = v*scale[ch] + shift[ch];
            As[c][r] = fmaxf(v, 0.0f);
        }
#pragma unroll
        for (int i = 0; i < 4; i++) {
            int idx = tid + i*256;
            int r = idx / TBN, c = idx % TBN;
            Bs[r][c] = W[(size_t)(k0 + r)*N + col0 + c];
        }
        __syncthreads();
#pragma unroll
        for (int kk = 0; kk < TBK; kk++) {
            float a[4], bb[4];
#pragma unroll
            for (int i = 0; i < 4; i++) a[i] = As[kk][ty*4+i];
#pragma unroll
            for (int j = 0; j < 4; j++) bb[j] = Bs[kk][tx*4+j];
#pragma unroll
            for (int i = 0; i < 4; i++)
#pragma unroll
                for (int j = 0; j < 4; j++)
                    acc[i][j] += a[i]*bb[j];
        }
        __syncthreads();
    }
#pragma unroll
    for (int i = 0; i < 4; i++) {
        size_t r = row0 + ty*4 + i;
#pragma unroll
        for (int j = 0; j < 4; j++) {
            int c = col0 + tx*4 + j;
            C[r*(size_t)N + c] = acc[i][j] + bias[c];
        }
    }
}

// --------- GEMM composing A = k[gather] - q + pos on the fly (K=256, N=64) ----
__global__ void gemm_attnpre_kernel(const float* __restrict__ W,
                                    const float* __restrict__ bias,
                                    float* __restrict__ C,
                                    int M, int N, int K)
{
    __shared__ float As[TBK][TBM];
    __shared__ float Bs[TBK][TBN];
    int tid = threadIdx.x;
    int row0 = blockIdx.y * TBM;
    int col0 = blockIdx.x * TBN;
    int tx = tid & 15, ty = tid >> 4;
    float acc[4][4] = {};
    for (int k0 = 0; k0 < K; k0 += TBK) {
#pragma unroll
        for (int i = 0; i < 4; i++) {
            int idx = tid + i*256;
            int r = idx / TBK, c = idx % TBK;
            size_t m = (size_t)(row0 + r);
            int cc = k0 + c;
            int bb = (int)(m >> 15);
            int nn = (int)((m >> 4) & 2047);
            int j  = g_nidx[m];
            float val = g_k[((size_t)bb*N1 + j)*D + cc]
                      - g_q[((size_t)bb*N1 + nn)*D + cc]
                      + g_pos[m*D + cc];
            As[c][r] = val;
        }
#pragma unroll
        for (int i = 0; i < 4; i++) {
            int idx = tid + i*256;
            int r = idx / TBN, c = idx % TBN;
            Bs[r][c] = W[(size_t)(k0 + r)*N + col0 + c];
        }
        __syncthreads();
#pragma unroll
        for (int kk = 0; kk < TBK; kk++) {
            float a[4], bb[4];
#pragma unroll
            for (int i = 0; i < 4; i++) a[i] = As[kk][ty*4+i];
#pragma unroll
            for (int j = 0; j < 4; j++) bb[j] = Bs[kk][tx*4+j];
#pragma unroll
            for (int i = 0; i < 4; i++)
#pragma unroll
                for (int j = 0; j < 4; j++)
                    acc[i][j] += a[i]*bb[j];
        }
        __syncthreads();
    }
#pragma unroll
    for (int i = 0; i < 4; i++) {
        size_t r = row0 + ty*4 + i;
#pragma unroll
        for (int j = 0; j < 4; j++) {
            int c = col0 + tx*4 + j;
            C[r*(size_t)N + c] = acc[i][j] + bias[c];
        }
    }
}

// ---------------- softmax over K neighbors + weighted aggregation --------------
__global__ void softmax_agg_kernel()
{
    int q = blockIdx.x;     // 0..8191
    int c = threadIdx.x;    // 0..255
    int b = q >> 11;
    __shared__ int sj[KNN];
    if (c < KNN) sj[c] = g_nidx[(size_t)q*KNN + c];
    __syncthreads();
    float a[KNN];
    size_t base = (size_t)q*KNN*D + c;
#pragma unroll
    for (int kk = 0; kk < KNN; kk++) a[kk] = g_attn[base + (size_t)kk*D];
    float mx = a[0];
#pragma unroll
    for (int kk = 1; kk < KNN; kk++) mx = fmaxf(mx, a[kk]);
    float s = 0.f;
#pragma unroll
    for (int kk = 0; kk < KNN; kk++) { a[kk] = expf(a[kk]-mx); s += a[kk]; }
    float inv = 1.0f / s;
    float x = 0.f;
#pragma unroll
    for (int kk = 0; kk < KNN; kk++) {
        float vv = g_v[((size_t)b*N1 + sj[kk])*D + c] + g_pos[base + (size_t)kk*D];
        x += vv * (a[kk]*inv);
    }
    g_x[(size_t)q*D + c] = x;
}

// =================================================================================
extern "C" void kernel_launch(void* const* d_in, const int* in_sizes, int n_in,
                              void* d_out, int out_size)
{
    const float* dec_x   = (const float*)d_in[0];
    const float* dec_pc  = (const float*)d_in[1];
    const float* enc_x   = (const float*)d_in[2];
    const float* enc_pc  = (const float*)d_in[3];
    const float* W_pre1  = (const float*)d_in[4];
    const float* b_pre1  = (const float*)d_in[5];
    const float* W_pre2  = (const float*)d_in[6];
    const float* b_pre2  = (const float*)d_in[7];
    const float* Wq      = (const float*)d_in[8];
    const float* bq      = (const float*)d_in[9];
    const float* Wk      = (const float*)d_in[10];
    const float* bk      = (const float*)d_in[11];
    const float* Wv      = (const float*)d_in[12];
    const float* bv      = (const float*)d_in[13];
    const float* Wp1     = (const float*)d_in[14];
    const float* bp1     = (const float*)d_in[15];
    const float* gp      = (const float*)d_in[16];
    const float* betap   = (const float*)d_in[17];
    const float* Wp2     = (const float*)d_in[18];
    const float* bp2     = (const float*)d_in[19];
    const float* Wa1     = (const float*)d_in[20];
    const float* ba1     = (const float*)d_in[21];
    const float* ga      = (const float*)d_in[22];
    const float* betaa   = (const float*)d_in[23];
    const float* Wa2     = (const float*)d_in[24];
    const float* ba2     = (const float*)d_in[25];
    const float* W_post1 = (const float*)d_in[26];
    const float* b_post1 = (const float*)d_in[27];
    const float* W_post2 = (const float*)d_in[28];
    const float* b_post2 = (const float*)d_in[29];
    float* out = (float*)d_out;

    // symbol addresses for buffers passed as GEMM args
    float *p_dx, *p_ex, *p_sx, *p_q, *p_k, *p_v, *p_hpos, *p_pos, *p_hattn, *p_attn, *p_x, *p_stats;
    cudaGetSymbolAddress((void**)&p_dx,    g_dx);
    cudaGetSymbolAddress((void**)&p_ex,    g_ex);
    cudaGetSymbolAddress((void**)&p_sx,    g_sx);
    cudaGetSymbolAddress((void**)&p_q,     g_q);
    cudaGetSymbolAddress((void**)&p_k,     g_k);
    cudaGetSymbolAddress((void**)&p_v,     g_v);
    cudaGetSymbolAddress((void**)&p_hpos,  g_hpos);
    cudaGetSymbolAddress((void**)&p_pos,   g_pos);
    cudaGetSymbolAddress((void**)&p_hattn, g_hattn);
    cudaGetSymbolAddress((void**)&p_attn,  g_attn);
    cudaGetSymbolAddress((void**)&p_x,     g_x);
    cudaGetSymbolAddress((void**)&p_stats, g_stats);

    const int M8 = B*N1;                         // 8192
    dim3 gemm8(D/TBN, M8/TBM);                   // (4,128)
    dim3 gemmPos(D/TBN, MROW/TBM);               // (4,2048)
    dim3 gemmAH(HA/TBN, MROW/TBM);               // (1,2048)

    // 1) pre-projections
    gemm_bias_kernel<<<gemm8, 256>>>(dec_x, W_pre1, b_pre1, nullptr, p_dx, M8, D, D);
    gemm_bias_kernel<<<gemm8, 256>>>(enc_x, W_pre2, b_pre2, nullptr, p_ex, M8, D, D);

    // 2) FPS (48KB dynamic smem)
    cudaFuncSetAttribute(fps_kernel, cudaFuncAttributeMaxDynamicSharedMemorySize, 3*NC*sizeof(float));
    fps_kernel<<<B, 1024, 3*NC*sizeof(float)>>>(dec_pc, enc_pc);

    // 3) gather sampled features + coords
    gather_kernel<<<M8, 256>>>(dec_pc, enc_pc);

    // 4) q/k/v
    gemm_bias_kernel<<<gemm8, 256>>>(p_dx, Wq, bq, nullptr, p_q, M8, D, D);
    gemm_bias_kernel<<<gemm8, 256>>>(p_sx, Wk, bk, nullptr, p_k, M8, D, D);
    gemm_bias_kernel<<<gemm8, 256>>>(p_sx, Wv, bv, nullptr, p_v, M8, D, D);

    // 5) KNN
    knn_kernel<<<dim3(N1/256, B), 256>>>(dec_pc);

    // 6) pos branch: h = pos_in@Wp1+b, stats, BN+ReLU fused into Wp2 GEMM
    zero_stats_kernel<<<1, 256>>>();
    hpos_kernel<<<MROW/4, 256>>>(dec_pc, Wp1, bp1);
    colstats_kernel<<<256, 256>>>(p_hpos, MROW, p_stats + 0, p_stats + 64);
    finalize_bn_kernel<<<1, 64>>>(p_stats + 0, p_stats + 64, gp, betap,
                                  1.0f/(float)MROW, p_stats + 256, p_stats + 320);
    gemm_bnrelu_kernel<<<gemmPos, 256>>>(p_hpos, Wp2, bp2, p_stats + 256, p_stats + 320,
                                         p_pos, MROW, D, HP);

    // 7) attn branch: h = (k_g - q + pos)@Wa1+b, stats, BN+ReLU fused into Wa2 GEMM
    gemm_attnpre_kernel<<<gemmAH, 256>>>(Wa1, ba1, p_hattn, MROW, HA, D);
    colstats_kernel<<<256, 256>>>(p_hattn, MROW, p_stats + 128, p_stats + 192);
    finalize_bn_kernel<<<1, 64>>>(p_stats + 128, p_stats + 192, ga, betaa,
                                  1.0f/(float)MROW, p_stats + 384, p_stats + 448);
    gemm_bnrelu_kernel<<<gemmPos, 256>>>(p_hattn, Wa2, ba2, p_stats + 384, p_stats + 448,
                                         p_attn, MROW, D, HA);

    // 8) softmax over neighbors + aggregation
    softmax_agg_kernel<<<M8, 256>>>();

    // 9) outputs
    float* out1 = out;                                   // [B,N1,256]
    float* opc1 = out + (size_t)M8*D;                    // [B,N1,3]
    float* out2 = opc1 + (size_t)M8*3;                   // [B,N1,256]
    float* opc2 = out2 + (size_t)M8*D;                   // [B,N2,3]
    gemm_bias_kernel<<<gemm8, 256>>>(p_x, W_post1, b_post1, dec_x, out1, M8, D, D);
    gemm_bias_kernel<<<gemm8, 256>>>(p_x, W_post2, b_post2, nullptr, out2, M8, D, D);
    cudaMemcpyAsync(opc1, dec_pc, (size_t)M8*3*sizeof(float), cudaMemcpyDeviceToDevice);
    cudaMemcpyAsync(opc2, enc_pc, (size_t)B*N2*3*sizeof(float), cudaMemcpyDeviceToDevice);
}

// round 4
// speedup vs baseline: 1.1101x; 1.1101x over previous
#include <cuda_runtime.h>
#include <cuda_bf16.h>
#include <math.h>

// Problem constants
#define B    4
#define N1   2048
#define N2   2048
#define NC   4096           // N1+N2
#define D    256
#define HP   64
#define HA   64
#define KNN  16
#define MROW (B*N1*KNN)     // 131072

// ---------------- scratch (device globals; no allocation allowed) -------------
__device__ float g_dx  [B*N1*D];
__device__ float g_ex  [B*N2*D];
__device__ float g_sx  [B*N1*D];
__device__ float g_spc [B*N1*3];
__device__ int   g_fidx[B*N1];
__device__ float g_qa  [B*N1*HA];
__device__ float g_ka  [B*N1*HA];
__device__ float g_v   [B*N1*D];
__device__ int   g_nidx[B*N1*KNN];
__device__ float g_hpos [MROW*HP];
__device__ float g_hattn[MROW*HA];
__device__ float g_x   [B*N1*D];
__device__ float g_WkWa1[D*HA];
__device__ float g_WqWa1[D*HA];
__device__ float g_Wp2a [HP*HA];
__device__ float g_cvec [HA];
// [0:64) psum [64:128) psq [128:192) asum [192:256) asq
// [256:320) pscale [320:384) pshift [384:448) ascale [448:512) ashift
__device__ float g_stats[512];

// ---------------- FPS: one block per batch, 512 threads, 1 barrier/iter -------
__global__ void fps_kernel(const float* __restrict__ decpc,
                           const float* __restrict__ encpc)
{
    extern __shared__ float sm[];
    float* sx = sm;
    float* sy = sm + NC;
    float* sz = sm + 2*NC;
    __shared__ float swv[2][16];
    __shared__ int   swi[2][16];

    int b = blockIdx.x;
    int tid = threadIdx.x;
    int wid = tid >> 5, lid = tid & 31;

    for (int j = tid; j < N1; j += 512) {
        sx[j] = decpc[((size_t)b*N1 + j)*3 + 0];
        sy[j] = decpc[((size_t)b*N1 + j)*3 + 1];
        sz[j] = decpc[((size_t)b*N1 + j)*3 + 2];
        sx[N1+j] = encpc[((size_t)b*N2 + j)*3 + 0];
        sy[N1+j] = encpc[((size_t)b*N2 + j)*3 + 1];
        sz[N1+j] = encpc[((size_t)b*N2 + j)*3 + 2];
    }
    float md[8];
#pragma unroll
    for (int t = 0; t < 8; t++) md[t] = 1e10f;
    if (tid == 0) g_fidx[b*N1] = 0;
    int cur = 0;
    __syncthreads();

    for (int i = 1; i < N1; i++) {
        float lx = sx[cur], ly = sy[cur], lz = sz[cur];
        float bestv = -1.0f; int besti = 0x7fffffff;
#pragma unroll
        for (int t = 0; t < 8; t++) {
            int j = tid + t*512;
            float ddx = sx[j]-lx, ddy = sy[j]-ly, ddz = sz[j]-lz;
            float d = ddx*ddx + ddy*ddy + ddz*ddz;
            float mm = fminf(md[t], d);
            md[t] = mm;
            if (mm > bestv) { bestv = mm; besti = j; }
        }
#pragma unroll
        for (int off = 16; off > 0; off >>= 1) {
            float ov = __shfl_down_sync(0xffffffffu, bestv, off);
            int   oi = __shfl_down_sync(0xffffffffu, besti, off);
            if (ov > bestv || (ov == bestv && oi < besti)) { bestv = ov; besti = oi; }
        }
        int pb = i & 1;
        if (lid == 0) { swv[pb][wid] = bestv; swi[pb][wid] = besti; }
        __syncthreads();
        bestv = swv[pb][0]; besti = swi[pb][0];
#pragma unroll
        for (int w = 1; w < 16; w++) {
            float ov = swv[pb][w]; int oi = swi[pb][w];
            if (ov > bestv || (ov == bestv && oi < besti)) { bestv = ov; besti = oi; }
        }
        cur = besti;
        if (tid == 0) g_fidx[b*N1 + i] = besti;
    }
}

// ---------------- gather sampled features + coords ----------------------------
__global__ void gather_kernel(const float* __restrict__ decpc,
                              const float* __restrict__ encpc)
{
    int row = blockIdx.x*4 + (threadIdx.x >> 6);
    int c4  = (threadIdx.x & 63) * 4;
    int b = row >> 11;
    int j = g_fidx[row];
    const float* src = (j < N1) ? &g_dx[((size_t)b*N1 + j)*D]
                                : &g_ex[((size_t)b*N2 + (j - N1))*D];
    *(float4*)&g_sx[(size_t)row*D + c4] = *(const float4*)&src[c4];
    if ((threadIdx.x & 63) < 3) {
        int cc = threadIdx.x & 63;
        const float* ps = (j < N1) ? &decpc[((size_t)b*N1 + j)*3]
                                   : &encpc[((size_t)b*N2 + (j - N1))*3];
        g_spc[(size_t)row*3 + cc] = ps[cc];
    }
}

// ---------------- KNN: one thread per query -----------------------------------
__global__ void knn_kernel(const float* __restrict__ decpc)
{
    __shared__ float px[N1], py[N1], pz[N1], s2s[N1];
    int b = blockIdx.y;
    int tid = threadIdx.x;
    for (int m = tid; m < N1; m += 256) {
        float x = g_spc[((size_t)b*N1 + m)*3 + 0];
        float y = g_spc[((size_t)b*N1 + m)*3 + 1];
        float z = g_spc[((size_t)b*N1 + m)*3 + 2];
        px[m] = x; py[m] = y; pz[m] = z;
        s2s[m] = x*x + y*y + z*z;
    }
    __syncthreads();
    int q = blockIdx.x*256 + tid;
    float qx = decpc[((size_t)b*N1 + q)*3 + 0];
    float qy = decpc[((size_t)b*N1 + q)*3 + 1];
    float qz = decpc[((size_t)b*N1 + q)*3 + 2];
    float s1 = qx*qx + qy*qy + qz*qz;
    float bd[KNN]; int bi[KNN];
#pragma unroll
    for (int t = 0; t < KNN; t++) { bd[t] = 1e30f; bi[t] = 0; }
    for (int m = 0; m < N1; m++) {
        float d = s1 + s2s[m] - 2.0f*(qx*px[m] + qy*py[m] + qz*pz[m]);
        if (d < bd[KNN-1]) {
            bd[KNN-1] = d; bi[KNN-1] = m;
#pragma unroll
            for (int t = KNN-1; t > 0; t--) {
                if (bd[t] < bd[t-1]) {
                    float td = bd[t]; bd[t] = bd[t-1]; bd[t-1] = td;
                    int   ti = bi[t]; bi[t] = bi[t-1]; bi[t-1] = ti;
                }
            }
        }
    }
#pragma unroll
    for (int t = 0; t < KNN; t++)
        g_nidx[((size_t)b*N1 + q)*KNN + t] = bi[t];
}

// ---------------- hpos: pos_in @ Wp1 + bp1 ------------------------------------
__global__ void hpos_kernel(const float* __restrict__ decpc,
                            const float* __restrict__ Wp1,
                            const float* __restrict__ bp1)
{
    int m = blockIdx.x*4 + (threadIdx.x >> 6);
    int c = threadIdx.x & 63;
    int b = m >> 15;
    int n = (m >> 4) & 2047;
    int j = g_nidx[m];
    const float* pp = &g_spc[((size_t)b*N1 + j)*3];
    const float* qq = &decpc[((size_t)b*N1 + n)*3];
    float p0 = pp[0]-qq[0], p1 = pp[1]-qq[1], p2 = pp[2]-qq[2];
    float h = p0*Wp1[c] + p1*Wp1[64+c] + p2*Wp1[128+c] + bp1[c];
    g_hpos[(size_t)m*HP + c] = h;
}

// ---------------- column stats over [M,64] matrix ------------------------------
__global__ void colstats_kernel(const float* __restrict__ X, int M,
                                float* __restrict__ sum, float* __restrict__ sumsq)
{
    int c  = threadIdx.x & 63;
    int rg = threadIdx.x >> 6;
    float s = 0.f, s2 = 0.f;
    for (int r = blockIdx.x*4 + rg; r < M; r += gridDim.x*4) {
        float v = X[(size_t)r*64 + c];
        s += v; s2 += v*v;
    }
    __shared__ float sh[256], sh2[256];
    sh[threadIdx.x] = s; sh2[threadIdx.x] = s2;
    __syncthreads();
    if (rg == 0) {
        s  = sh[c]  + sh[64+c]  + sh[128+c]  + sh[192+c];
        s2 = sh2[c] + sh2[64+c] + sh2[128+c] + sh2[192+c];
        atomicAdd(&sum[c], s);
        atomicAdd(&sumsq[c], s2);
    }
}

__global__ void zero_stats_kernel() { g_stats[threadIdx.x] = 0.0f; }

__global__ void finalize_bn_kernel(const float* __restrict__ sum,
                                   const float* __restrict__ sumsq,
                                   const float* __restrict__ g,
                                   const float* __restrict__ beta,
                                   float invM,
                                   float* __restrict__ scale,
                                   float* __restrict__ shift)
{
    int c = threadIdx.x;
    float mean = sum[c]*invM;
    float var  = sumsq[c]*invM - mean*mean;
    float sc = g[c]*rsqrtf(var + 1e-5f);
    scale[c] = sc;
    shift[c] = beta[c] - mean*sc;
}

// ---------------- cvec = (bk - bq + bp2) @ Wa1 + ba1 --------------------------
__global__ void cvec_kernel(const float* __restrict__ bk,
                            const float* __restrict__ bq,
                            const float* __restrict__ bp2,
                            const float* __restrict__ Wa1,
                            const float* __restrict__ ba1)
{
    int c = threadIdx.x;
    float s = ba1[c];
    for (int i = 0; i < D; i++)
        s += (bk[i] - bq[i] + bp2[i]) * Wa1[(size_t)i*HA + c];
    g_cvec[c] = s;
}

// ---------------- small tiled GEMM 64x64 tile (N<=64 shapes) -------------------
#define TBM 64
#define TBN 64
#define TBK 16

__global__ void gemm_bias_kernel(const float* __restrict__ A,
                                 const float* __restrict__ W,
                                 const float* __restrict__ bias,
                                 const float* __restrict__ resid,
                                 float* __restrict__ C,
                                 int M, int N, int K)
{
    __shared__ float As[TBK][TBM];
    __shared__ float Bs[TBK][TBN];
    int tid = threadIdx.x;
    int row0 = blockIdx.y * TBM;
    int col0 = blockIdx.x * TBN;
    int tx = tid & 15, ty = tid >> 4;
    float acc[4][4] = {};
    for (int k0 = 0; k0 < K; k0 += TBK) {
#pragma unroll
        for (int i = 0; i < 4; i++) {
            int idx = tid + i*256;
            int r = idx / TBK, c = idx % TBK;
            As[c][r] = A[(size_t)(row0 + r)*K + k0 + c];
        }
#pragma unroll
        for (int i = 0; i < 4; i++) {
            int idx = tid + i*256;
            int r = idx / TBN, c = idx % TBN;
            Bs[r][c] = W[(size_t)(k0 + r)*N + col0 + c];
        }
        __syncthreads();
#pragma unroll
        for (int kk = 0; kk < TBK; kk++) {
            float a[4], bb[4];
#pragma unroll
            for (int i = 0; i < 4; i++) a[i] = As[kk][ty*4+i];
#pragma unroll
            for (int j = 0; j < 4; j++) bb[j] = Bs[kk][tx*4+j];
#pragma unroll
            for (int i = 0; i < 4; i++)
#pragma unroll
                for (int j = 0; j < 4; j++)
                    acc[i][j] += a[i]*bb[j];
        }
        __syncthreads();
    }
#pragma unroll
    for (int i = 0; i < 4; i++) {
        size_t r = row0 + ty*4 + i;
#pragma unroll
        for (int j = 0; j < 4; j++) {
            int c = col0 + tx*4 + j;
            float v = acc[i][j];
            if (bias)  v += bias[c];
            if (resid) v += resid[r*(size_t)N + c];
            C[r*(size_t)N + c] = v;
        }
    }
}

// ---------------- big GEMM: 128x128 tile, 8x8 microtile ------------------------
#define GM 128
#define GN 128
#define GK 16

__global__ void __launch_bounds__(256, 2)
gemm128_kernel(const float* __restrict__ A,
               const float* __restrict__ W,
               const float* __restrict__ bias,
               const float* __restrict__ resid,
               float* __restrict__ C,
               int M, int N, int K)
{
    __shared__ float As[GK][GM+4];   // pitch 132
    __shared__ float Bs[GK][GN];
    int tid = threadIdx.x;
    int row0 = blockIdx.y * GM;
    int col0 = blockIdx.x * GN;
    int tx = tid & 15, ty = tid >> 4;
    float acc[8][8] = {};
    for (int k0 = 0; k0 < K; k0 += GK) {
#pragma unroll
        for (int i = 0; i < 2; i++) {
            int p = tid + i*256;          // 0..511
            int r = p >> 2, kq = (p & 3) * 4;
            float4 va = *(const float4*)&A[(size_t)(row0 + r)*K + k0 + kq];
            As[kq+0][r] = va.x; As[kq+1][r] = va.y;
            As[kq+2][r] = va.z; As[kq+3][r] = va.w;
        }
#pragma unroll
        for (int i = 0; i < 2; i++) {
            int p = tid + i*256;
            int r = p >> 5, cq = (p & 31) * 4;
            *(float4*)&Bs[r][cq] = *(const float4*)&W[(size_t)(k0 + r)*N + col0 + cq];
        }
        __syncthreads();
#pragma unroll
        for (int kk = 0; kk < GK; kk++) {
            float4 a0 = *(const float4*)&As[kk][ty*8];
            float4 a1 = *(const float4*)&As[kk][ty*8+4];
            float4 b0 = *(const float4*)&Bs[kk][tx*8];
            float4 b1 = *(const float4*)&Bs[kk][tx*8+4];
            float a[8] = {a0.x,a0.y,a0.z,a0.w,a1.x,a1.y,a1.z,a1.w};
            float bb[8] = {b0.x,b0.y,b0.z,b0.w,b1.x,b1.y,b1.z,b1.w};
#pragma unroll
            for (int i = 0; i < 8; i++)
#pragma unroll
                for (int j = 0; j < 8; j++)
                    acc[i][j] += a[i]*bb[j];
        }
        __syncthreads();
    }
#pragma unroll
    for (int i = 0; i < 8; i++) {
        size_t r = row0 + ty*8 + i;
#pragma unroll
        for (int j = 0; j < 8; j++) {
            int c = col0 + tx*8 + j;
            float v = acc[i][j];
            if (bias)  v += bias[c];
            if (resid) v += resid[r*(size_t)N + c];
            C[r*(size_t)N + c] = v;
        }
    }
}

// ---- hattn = relu(bn_pos(hp)) @ Wp2a + ka[gather] - qa + cvec  ([M,64]) ------
__global__ void __launch_bounds__(256)
hattn_kernel()
{
    __shared__ float Aw[64][65];
    __shared__ float Bw[64*64];
    int tid = threadIdx.x;
    int m0 = blockIdx.x * 64;
#pragma unroll
    for (int i = 0; i < 16; i++) {
        int idx = tid + i*256;
        int r = idx >> 6, k = idx & 63;
        float h = g_hpos[(size_t)(m0+r)*64 + k];
        Aw[r][k] = fmaxf(h*g_stats[256+k] + g_stats[320+k], 0.0f);
        Bw[idx] = g_Wp2a[idx];
    }
    __syncthreads();
    int tx = tid & 15, ty = tid >> 4;
    float acc[4][4] = {};
#pragma unroll 4
    for (int kk = 0; kk < 64; kk++) {
        float a[4], bb[4];
#pragma unroll
        for (int i = 0; i < 4; i++) a[i] = Aw[ty*4+i][kk];
#pragma unroll
        for (int j = 0; j < 4; j++) bb[j] = Bw[kk*64 + tx*4 + j];
#pragma unroll
        for (int i = 0; i < 4; i++)
#pragma unroll
            for (int j = 0; j < 4; j++)
                acc[i][j] += a[i]*bb[j];
    }
#pragma unroll
    for (int i = 0; i < 4; i++) {
        int m = m0 + ty*4 + i;
        int b = m >> 15;
        int n = (m >> 4) & 2047;
        int jj = g_nidx[m];
        const float* kar = &g_ka[(((size_t)b<<11) + jj)*HA];
        const float* qar = &g_qa[(((size_t)b<<11) + n )*HA];
#pragma unroll
        for (int j = 0; j < 4; j++) {
            int c = tx*4 + j;
            g_hattn[(size_t)m*HA + c] = acc[i][j] + kar[c] - qar[c] + g_cvec[c];
        }
    }
}

// ---- fused: attn GEMM + pos GEMM + softmax(K) + aggregation -> g_x -----------
// block: 64 rows (4 queries x 16 neighbors) x 128 cols; grid (2, 2048)
__global__ void __launch_bounds__(256, 2)
attnout_kernel(const float* __restrict__ Wa2,
               const float* __restrict__ ba2,
               const float* __restrict__ Wp2,
               const float* __restrict__ bp2)
{
    extern __shared__ float sm[];
    float* Ah     = sm;                 // [64][65]
    float* Ap     = Ah + 64*65;         // [64][65]
    float* attn_s = Ap + 64*65;         // [64][132]
    float* pos_s  = attn_s + 64*132;    // [64][132]
    float* Bs     = pos_s + 64*132;     // [16][128]
    int*   sj     = (int*)(Bs + 16*128);// [64]

    int tid = threadIdx.x;
    int m0 = blockIdx.y * 64;
    int c0 = blockIdx.x * 128;
    int tx = tid & 15, ty = tid >> 4;

#pragma unroll
    for (int i = 0; i < 16; i++) {
        int idx = tid + i*256;
        int r = idx >> 6, k = idx & 63;
        float ha = g_hattn[(size_t)(m0+r)*64 + k];
        Ah[r*65 + k] = fmaxf(ha*g_stats[384+k] + g_stats[448+k], 0.0f);
        float hp = g_hpos[(size_t)(m0+r)*64 + k];
        Ap[r*65 + k] = fmaxf(hp*g_stats[256+k] + g_stats[320+k], 0.0f);
    }
    if (tid < 64) sj[tid] = g_nidx[m0 + tid];
    __syncthreads();

    // ---- GEMM1: attn_s = relu_bn(hattn) @ Wa2 + ba2
    {
        float acc[4][8] = {};
        for (int k0 = 0; k0 < 64; k0 += 16) {
            __syncthreads();
#pragma unroll
            for (int i = 0; i < 2; i++) {
                int p = tid + i*256;
                int r = p >> 5, cq = (p & 31)*4;
                *(float4*)&Bs[r*128 + cq] = *(const float4*)&Wa2[(size_t)(k0+r)*D + c0 + cq];
            }
            __syncthreads();
#pragma unroll
            for (int kk = 0; kk < 16; kk++) {
                float a[4];
#pragma unroll
                for (int i = 0; i < 4; i++) a[i] = Ah[(ty*4+i)*65 + k0 + kk];
                float4 b0 = *(const float4*)&Bs[kk*128 + tx*8];
                float4 b1 = *(const float4*)&Bs[kk*128 + tx*8 + 4];
                float bb[8] = {b0.x,b0.y,b0.z,b0.w,b1.x,b1.y,b1.z,b1.w};
#pragma unroll
                for (int i = 0; i < 4; i++)
#pragma unroll
                    for (int j = 0; j < 8; j++)
                        acc[i][j] += a[i]*bb[j];
            }
        }
#pragma unroll
        for (int i = 0; i < 4; i++)
#pragma unroll
            for (int j = 0; j < 8; j++)
                attn_s[(ty*4+i)*132 + tx*8 + j] = acc[i][j] + ba2[c0 + tx*8 + j];
    }
    // ---- GEMM2: pos_s = relu_bn(hp) @ Wp2 + bp2
    {
        float acc[4][8] = {};
        for (int k0 = 0; k0 < 64; k0 += 16) {
            __syncthreads();
#pragma unroll
            for (int i = 0; i < 2; i++) {
                int p = tid + i*256;
                int r = p >> 5, cq = (p & 31)*4;
                *(float4*)&Bs[r*128 + cq] = *(const float4*)&Wp2[(size_t)(k0+r)*D + c0 + cq];
            }
            __syncthreads();
#pragma unroll
            for (int kk = 0; kk < 16; kk++) {
                float a[4];
#pragma unroll
                for (int i = 0; i < 4; i++) a[i] = Ap[(ty*4+i)*65 + k0 + kk];
                float4 b0 = *(const float4*)&Bs[kk*128 + tx*8];
                float4 b1 = *(const float4*)&Bs[kk*128 + tx*8 + 4];
                float bb[8] = {b0.x,b0.y,b0.z,b0.w,b1.x,b1.y,b1.z,b1.w};
#pragma unroll
                for (int i = 0; i < 4; i++)
#pragma unroll
                    for (int j = 0; j < 8; j++)
                        acc[i][j] += a[i]*bb[j];
            }
        }
#pragma unroll
        for (int i = 0; i < 4; i++)
#pragma unroll
            for (int j = 0; j < 8; j++)
                pos_s[(ty*4+i)*132 + tx*8 + j] = acc[i][j] + bp2[c0 + tx*8 + j];
    }
    __syncthreads();

    // ---- softmax over 16 neighbors + aggregation
#pragma unroll
    for (int e = tid; e < 512; e += 256) {
        int q = e >> 7;            // 0..3
        int c = e & 127;
        int mrow = q*16;
        float mx = -1e30f;
#pragma unroll
        for (int k = 0; k < KNN; k++)
            mx = fmaxf(mx, attn_s[(mrow+k)*132 + c]);
        float w[KNN]; float s = 0.f;
#pragma unroll
        for (int k = 0; k < KNN; k++) {
            w[k] = __expf(attn_s[(mrow+k)*132 + c] - mx);
            s += w[k];
        }
        float inv = 1.0f / s;
        int qg = (m0 >> 4) + q;
        int b = qg >> 11;
        float x = 0.f;
#pragma unroll
        for (int k = 0; k < KNN; k++) {
            int j = sj[mrow + k];
            float vv = g_v[(((size_t)b<<11) + j)*D + c0 + c] + pos_s[(mrow+k)*132 + c];
            x += vv * w[k];
        }
        g_x[(size_t)qg*D + c0 + c] = x * inv;
    }
}

// =================================================================================
extern "C" void kernel_launch(void* const* d_in, const int* in_sizes, int n_in,
                              void* d_out, int out_size)
{
    const float* dec_x   = (const float*)d_in[0];
    const float* dec_pc  = (const float*)d_in[1];
    const float* enc_x   = (const float*)d_in[2];
    const float* enc_pc  = (const float*)d_in[3];
    const float* W_pre1  = (const float*)d_in[4];
    const float* b_pre1  = (const float*)d_in[5];
    const float* W_pre2  = (const float*)d_in[6];
    const float* b_pre2  = (const float*)d_in[7];
    const float* Wq      = (const float*)d_in[8];
    const float* bq      = (const float*)d_in[9];
    const float* Wk      = (const float*)d_in[10];
    const float* bk      = (const float*)d_in[11];
    const float* Wv      = (const float*)d_in[12];
    const float* bv      = (const float*)d_in[13];
    const float* Wp1     = (const float*)d_in[14];
    const float* bp1     = (const float*)d_in[15];
    const float* gp      = (const float*)d_in[16];
    const float* betap   = (const float*)d_in[17];
    const float* Wp2     = (const float*)d_in[18];
    const float* bp2     = (const float*)d_in[19];
    const float* Wa1     = (const float*)d_in[20];
    const float* ba1     = (const float*)d_in[21];
    const float* ga      = (const float*)d_in[22];
    const float* betaa   = (const float*)d_in[23];
    const float* Wa2     = (const float*)d_in[24];
    const float* ba2     = (const float*)d_in[25];
    const float* W_post1 = (const float*)d_in[26];
    const float* b_post1 = (const float*)d_in[27];
    const float* W_post2 = (const float*)d_in[28];
    const float* b_post2 = (const float*)d_in[29];
    float* out = (float*)d_out;

    float *p_dx, *p_ex, *p_sx, *p_qa, *p_ka, *p_v, *p_hpos, *p_hattn, *p_x;
    float *p_WkWa1, *p_WqWa1, *p_Wp2a, *p_stats;
    cudaGetSymbolAddress((void**)&p_dx,    g_dx);
    cudaGetSymbolAddress((void**)&p_ex,    g_ex);
    cudaGetSymbolAddress((void**)&p_sx,    g_sx);
    cudaGetSymbolAddress((void**)&p_qa,    g_qa);
    cudaGetSymbolAddress((void**)&p_ka,    g_ka);
    cudaGetSymbolAddress((void**)&p_v,     g_v);
    cudaGetSymbolAddress((void**)&p_hpos,  g_hpos);
    cudaGetSymbolAddress((void**)&p_hattn, g_hattn);
    cudaGetSymbolAddress((void**)&p_x,     g_x);
    cudaGetSymbolAddress((void**)&p_WkWa1, g_WkWa1);
    cudaGetSymbolAddress((void**)&p_WqWa1, g_WqWa1);
    cudaGetSymbolAddress((void**)&p_Wp2a,  g_Wp2a);
    cudaGetSymbolAddress((void**)&p_stats, g_stats);

    const int M8 = B*N1;                         // 8192
    dim3 g128(D/GN, M8/GM);                      // (2,64)

    // 0) weight precomputes + constants
    gemm_bias_kernel<<<dim3(1, 4), 256>>>(Wk,  Wa1, nullptr, nullptr, p_WkWa1, D,  HA, D);
    gemm_bias_kernel<<<dim3(1, 4), 256>>>(Wq,  Wa1, nullptr, nullptr, p_WqWa1, D,  HA, D);
    gemm_bias_kernel<<<dim3(1, 1), 256>>>(Wp2, Wa1, nullptr, nullptr, p_Wp2a,  HP, HA, D);
    cvec_kernel<<<1, HA>>>(bk, bq, bp2, Wa1, ba1);
    zero_stats_kernel<<<1, 256>>>();

    // 1) pre-projections
    gemm128_kernel<<<g128, 256>>>(dec_x, W_pre1, b_pre1, nullptr, p_dx, M8, D, D);
    gemm128_kernel<<<g128, 256>>>(enc_x, W_pre2, b_pre2, nullptr, p_ex, M8, D, D);

    // 2) FPS
    cudaFuncSetAttribute(fps_kernel, cudaFuncAttributeMaxDynamicSharedMemorySize, 3*NC*sizeof(float));
    fps_kernel<<<B, 512, 3*NC*sizeof(float)>>>(dec_pc, enc_pc);

    // 3) gather sampled features + coords
    gather_kernel<<<M8/4, 256>>>(dec_pc, enc_pc);

    // 4) qa/ka/v
    gemm_bias_kernel<<<dim3(1, 128), 256>>>(p_dx, p_WqWa1, nullptr, nullptr, p_qa, M8, HA, D);
    gemm_bias_kernel<<<dim3(1, 128), 256>>>(p_sx, p_WkWa1, nullptr, nullptr, p_ka, M8, HA, D);
    gemm128_kernel<<<g128, 256>>>(p_sx, Wv, bv, nullptr, p_v, M8, D, D);

    // 5) KNN
    knn_kernel<<<dim3(N1/256, B), 256>>>(dec_pc);

    // 6) pos branch hidden + BN stats
    hpos_kernel<<<MROW/4, 256>>>(dec_pc, Wp1, bp1);
    colstats_kernel<<<256, 256>>>(p_hpos, MROW, p_stats + 0, p_stats + 64);
    finalize_bn_kernel<<<1, 64>>>(p_stats + 0, p_stats + 64, gp, betap,
                                  1.0f/(float)MROW, p_stats + 256, p_stats + 320);

    // 7) hattn compose + BN stats
    hattn_kernel<<<MROW/64, 256>>>();
    colstats_kernel<<<256, 256>>>(p_hattn, MROW, p_stats + 128, p_stats + 192);
    finalize_bn_kernel<<<1, 64>>>(p_stats + 128, p_stats + 192, ga, betaa,
                                  1.0f/(float)MROW, p_stats + 384, p_stats + 448);

    // 8) fused attn/pos GEMMs + softmax + aggregation
    cudaFuncSetAttribute(attnout_kernel, cudaFuncAttributeMaxDynamicSharedMemorySize, 112*1024);
    size_t smbytes = (size_t)(64*65*2 + 64*132*2 + 16*128)*sizeof(float) + 64*sizeof(int);
    attnout_kernel<<<dim3(2, MROW/64), 256, smbytes>>>(Wa2, ba2, Wp2, bp2);

    // 9) outputs
    float* out1 = out;                                   // [B,N1,256]
    float* opc1 = out + (size_t)M8*D;                    // [B,N1,3]
    float* out2 = opc1 + (size_t)M8*3;                   // [B,N1,256]
    float* opc2 = out2 + (size_t)M8*D;                   // [B,N2,3]
    gemm128_kernel<<<g128, 256>>>(p_x, W_post1, b_post1, dec_x, out1, M8, D, D);
    gemm128_kernel<<<g128, 256>>>(p_x, W_post2, b_post2, nullptr, out2, M8, D, D);
    cudaMemcpyAsync(opc1, dec_pc, (size_t)M8*3*sizeof(float), cudaMemcpyDeviceToDevice);
    cudaMemcpyAsync(opc2, enc_pc, (size_t)B*N2*3*sizeof(float), cudaMemcpyDeviceToDevice);
}

// round 5
// speedup vs baseline: 1.3061x; 1.1765x over previous
#include <cuda_runtime.h>
#include <cuda_bf16.h>
#include <math.h>

// Problem constants
#define B    4
#define N1   2048
#define N2   2048
#define NC   4096           // N1+N2
#define D    256
#define HP   64
#define HA   64
#define KNN  16
#define MROW (B*N1*KNN)     // 131072

// ---------------- scratch (device globals; no allocation allowed) -------------
__device__ float g_dx  [B*N1*D];
__device__ float g_ex  [B*N2*D];
__device__ float g_sx  [B*N1*D];
__device__ float g_spc [B*N1*3];
__device__ int   g_fidx[B*N1];
__device__ float g_qa  [B*N1*HA];
__device__ float g_ka  [B*N1*HA];
__device__ float g_v   [B*N1*D];
__device__ int   g_nidx[B*N1*KNN];
__device__ float g_hpos [MROW*HP];
__device__ float g_hattn[MROW*HA];
__device__ float g_x   [B*N1*D];
__device__ float g_WkWa1[D*HA];
__device__ float g_WqWa1[D*HA];
__device__ float g_Wp2a [HP*HA];
__device__ float g_cvec [HA];
// [0:64) psum [64:128) psq [128:192) asum [192:256) asq
// [256:320) pscale [320:384) pshift [384:448) ascale [448:512) ashift
__device__ float g_stats[512];

// ---------------- FPS: one block per batch, 512 threads, redux-based ----------
__global__ void fps_kernel(const float* __restrict__ decpc,
                           const float* __restrict__ encpc)
{
    extern __shared__ float sm[];
    float* sx = sm;
    float* sy = sm + NC;
    float* sz = sm + 2*NC;
    __shared__ unsigned long long swk[2][16];

    int b = blockIdx.x;
    int tid = threadIdx.x;
    int wid = tid >> 5, lid = tid & 31;

    for (int j = tid; j < N1; j += 512) {
        sx[j] = decpc[((size_t)b*N1 + j)*3 + 0];
        sy[j] = decpc[((size_t)b*N1 + j)*3 + 1];
        sz[j] = decpc[((size_t)b*N1 + j)*3 + 2];
        sx[N1+j] = encpc[((size_t)b*N2 + j)*3 + 0];
        sy[N1+j] = encpc[((size_t)b*N2 + j)*3 + 1];
        sz[N1+j] = encpc[((size_t)b*N2 + j)*3 + 2];
    }
    float md[8];
#pragma unroll
    for (int t = 0; t < 8; t++) md[t] = 1e10f;
    if (tid == 0) g_fidx[b*N1] = 0;
    int cur = 0;
    __syncthreads();

    for (int i = 1; i < N1; i++) {
        float lx = sx[cur], ly = sy[cur], lz = sz[cur];
        float bestv = -1.0f; int besti = 0x7fffffff;
#pragma unroll
        for (int t = 0; t < 8; t++) {
            int j = tid + t*512;
            float ddx = sx[j]-lx, ddy = sy[j]-ly, ddz = sz[j]-lz;
            float d = ddx*ddx + ddy*ddy + ddz*ddz;
            float mm = fminf(md[t], d);
            md[t] = mm;
            if (mm > bestv) { bestv = mm; besti = j; }
        }
        // warp reduce via redux: max on order-preserving key, then min index
        unsigned kb = __float_as_uint(bestv);
        kb = ((int)kb < 0) ? ~kb : (kb | 0x80000000u);
        unsigned mk;
        asm("redux.sync.max.u32 %0, %1, 0xffffffff;" : "=r"(mk) : "r"(kb));
        unsigned idxc = (kb == mk) ? (unsigned)besti : 0xffffffffu;
        unsigned mi;
        asm("redux.sync.min.u32 %0, %1, 0xffffffff;" : "=r"(mi) : "r"(idxc));
        int pb = i & 1;
        if (lid == 0)
            swk[pb][wid] = (((unsigned long long)mk) << 32) | (unsigned long long)(0xffffffffu - mi);
        __syncthreads();
        unsigned long long best = swk[pb][0];
#pragma unroll
        for (int w = 1; w < 16; w++) {
            unsigned long long o = swk[pb][w];
            best = (o > best) ? o : best;
        }
        cur = (int)(0xffffffffu - (unsigned)best);
        if (tid == 0) g_fidx[b*N1 + i] = cur;
    }
}

// ---------------- gather sampled features + coords ----------------------------
__global__ void gather_kernel(const float* __restrict__ decpc,
                              const float* __restrict__ encpc)
{
    int row = blockIdx.x*4 + (threadIdx.x >> 6);
    int c4  = (threadIdx.x & 63) * 4;
    int b = row >> 11;
    int j = g_fidx[row];
    const float* src = (j < N1) ? &g_dx[((size_t)b*N1 + j)*D]
                                : &g_ex[((size_t)b*N2 + (j - N1))*D];
    *(float4*)&g_sx[(size_t)row*D + c4] = *(const float4*)&src[c4];
    if ((threadIdx.x & 63) < 3) {
        int cc = threadIdx.x & 63;
        const float* ps = (j < N1) ? &decpc[((size_t)b*N1 + j)*3]
                                   : &encpc[((size_t)b*N2 + (j - N1))*3];
        g_spc[(size_t)row*3 + cc] = ps[cc];
    }
}

// ---------------- KNN: one thread per query -----------------------------------
__global__ void knn_kernel(const float* __restrict__ decpc)
{
    __shared__ float px[N1], py[N1], pz[N1], s2s[N1];
    int b = blockIdx.y;
    int tid = threadIdx.x;
    for (int m = tid; m < N1; m += 256) {
        float x = g_spc[((size_t)b*N1 + m)*3 + 0];
        float y = g_spc[((size_t)b*N1 + m)*3 + 1];
        float z = g_spc[((size_t)b*N1 + m)*3 + 2];
        px[m] = x; py[m] = y; pz[m] = z;
        s2s[m] = x*x + y*y + z*z;
    }
    __syncthreads();
    int q = blockIdx.x*256 + tid;
    float qx = decpc[((size_t)b*N1 + q)*3 + 0];
    float qy = decpc[((size_t)b*N1 + q)*3 + 1];
    float qz = decpc[((size_t)b*N1 + q)*3 + 2];
    float s1 = qx*qx + qy*qy + qz*qz;
    float bd[KNN]; int bi[KNN];
#pragma unroll
    for (int t = 0; t < KNN; t++) { bd[t] = 1e30f; bi[t] = 0; }
    for (int m = 0; m < N1; m++) {
        float d = s1 + s2s[m] - 2.0f*(qx*px[m] + qy*py[m] + qz*pz[m]);
        if (d < bd[KNN-1]) {
            bd[KNN-1] = d; bi[KNN-1] = m;
#pragma unroll
            for (int t = KNN-1; t > 0; t--) {
                if (bd[t] < bd[t-1]) {
                    float td = bd[t]; bd[t] = bd[t-1]; bd[t-1] = td;
                    int   ti = bi[t]; bi[t] = bi[t-1]; bi[t-1] = ti;
                }
            }
        }
    }
#pragma unroll
    for (int t = 0; t < KNN; t++)
        g_nidx[((size_t)b*N1 + q)*KNN + t] = bi[t];
}

// ---------------- hpos: pos_in @ Wp1 + bp1 ------------------------------------
__global__ void hpos_kernel(const float* __restrict__ decpc,
                            const float* __restrict__ Wp1,
                            const float* __restrict__ bp1)
{
    int m = blockIdx.x*4 + (threadIdx.x >> 6);
    int c = threadIdx.x & 63;
    int b = m >> 15;
    int n = (m >> 4) & 2047;
    int j = g_nidx[m];
    const float* pp = &g_spc[((size_t)b*N1 + j)*3];
    const float* qq = &decpc[((size_t)b*N1 + n)*3];
    float p0 = pp[0]-qq[0], p1 = pp[1]-qq[1], p2 = pp[2]-qq[2];
    float h = p0*Wp1[c] + p1*Wp1[64+c] + p2*Wp1[128+c] + bp1[c];
    g_hpos[(size_t)m*HP + c] = h;
}

// ---------------- column stats over [M,64] matrix ------------------------------
__global__ void colstats_kernel(const float* __restrict__ X, int M,
                                float* __restrict__ sum, float* __restrict__ sumsq)
{
    int c  = threadIdx.x & 63;
    int rg = threadIdx.x >> 6;
    float s = 0.f, s2 = 0.f;
    for (int r = blockIdx.x*4 + rg; r < M; r += gridDim.x*4) {
        float v = X[(size_t)r*64 + c];
        s += v; s2 += v*v;
    }
    __shared__ float sh[256], sh2[256];
    sh[threadIdx.x] = s; sh2[threadIdx.x] = s2;
    __syncthreads();
    if (rg == 0) {
        s  = sh[c]  + sh[64+c]  + sh[128+c]  + sh[192+c];
        s2 = sh2[c] + sh2[64+c] + sh2[128+c] + sh2[192+c];
        atomicAdd(&sum[c], s);
        atomicAdd(&sumsq[c], s2);
    }
}

__global__ void zero_stats_kernel() { g_stats[threadIdx.x] = 0.0f; }

__global__ void finalize_bn_kernel(const float* __restrict__ sum,
                                   const float* __restrict__ sumsq,
                                   const float* __restrict__ g,
                                   const float* __restrict__ beta,
                                   float invM,
                                   float* __restrict__ scale,
                                   float* __restrict__ shift)
{
    int c = threadIdx.x;
    float mean = sum[c]*invM;
    float var  = sumsq[c]*invM - mean*mean;
    float sc = g[c]*rsqrtf(var + 1e-5f);
    scale[c] = sc;
    shift[c] = beta[c] - mean*sc;
}

// ---------------- cvec = (bk - bq + bp2) @ Wa1 + ba1 (parallel) ----------------
__global__ void cvec_kernel(const float* __restrict__ bk,
                            const float* __restrict__ bq,
                            const float* __restrict__ bp2,
                            const float* __restrict__ Wa1,
                            const float* __restrict__ ba1)
{
    int c = threadIdx.x & 63;
    int part = threadIdx.x >> 6;
    float s = 0.f;
    for (int i = part*64; i < part*64 + 64; i++)
        s += (bk[i] - bq[i] + bp2[i]) * Wa1[(size_t)i*HA + c];
    __shared__ float sh[256];
    sh[threadIdx.x] = s;
    __syncthreads();
    if (part == 0)
        g_cvec[c] = sh[c] + sh[64+c] + sh[128+c] + sh[192+c] + ba1[c];
}

// ---------------- small tiled GEMM 64x64 tile (weight precomputes) -------------
#define TBM 64
#define TBN 64
#define TBK 16

__global__ void gemm_bias_kernel(const float* __restrict__ A,
                                 const float* __restrict__ W,
                                 const float* __restrict__ bias,
                                 const float* __restrict__ resid,
                                 float* __restrict__ C,
                                 int M, int N, int K)
{
    __shared__ float As[TBK][TBM];
    __shared__ float Bs[TBK][TBN];
    int tid = threadIdx.x;
    int row0 = blockIdx.y * TBM;
    int col0 = blockIdx.x * TBN;
    int tx = tid & 15, ty = tid >> 4;
    float acc[4][4] = {};
    for (int k0 = 0; k0 < K; k0 += TBK) {
#pragma unroll
        for (int i = 0; i < 4; i++) {
            int idx = tid + i*256;
            int r = idx / TBK, c = idx % TBK;
            As[c][r] = A[(size_t)(row0 + r)*K + k0 + c];
        }
#pragma unroll
        for (int i = 0; i < 4; i++) {
            int idx = tid + i*256;
            int r = idx / TBN, c = idx % TBN;
            Bs[r][c] = W[(size_t)(k0 + r)*N + col0 + c];
        }
        __syncthreads();
#pragma unroll
        for (int kk = 0; kk < TBK; kk++) {
            float a[4], bb[4];
#pragma unroll
            for (int i = 0; i < 4; i++) a[i] = As[kk][ty*4+i];
#pragma unroll
            for (int j = 0; j < 4; j++) bb[j] = Bs[kk][tx*4+j];
#pragma unroll
            for (int i = 0; i < 4; i++)
#pragma unroll
                for (int j = 0; j < 4; j++)
                    acc[i][j] += a[i]*bb[j];
        }
        __syncthreads();
    }
#pragma unroll
    for (int i = 0; i < 4; i++) {
        size_t r = row0 + ty*4 + i;
#pragma unroll
        for (int j = 0; j < 4; j++) {
            int c = col0 + tx*4 + j;
            float v = acc[i][j];
            if (bias)  v += bias[c];
            if (resid) v += resid[r*(size_t)N + c];
            C[r*(size_t)N + c] = v;
        }
    }
}

// ---------------- N=64 GEMM: 128x64 tile, 8x4 microtile (qa & ka in one) ------
__global__ void __launch_bounds__(256, 2)
gemm_n64_kernel(const float* __restrict__ A0, const float* __restrict__ A1,
                const float* __restrict__ W0, const float* __restrict__ W1,
                float* __restrict__ C0, float* __restrict__ C1)
{
    const float* A = blockIdx.x ? A1 : A0;
    const float* W = blockIdx.x ? W1 : W0;
    float*       C = blockIdx.x ? C1 : C0;
    __shared__ float As[16][132];
    __shared__ float Bs[16][64];
    int tid = threadIdx.x;
    int row0 = blockIdx.y * 128;
    int tx = tid & 15, ty = tid >> 4;
    float acc[8][4] = {};
    for (int k0 = 0; k0 < D; k0 += 16) {
#pragma unroll
        for (int i = 0; i < 2; i++) {
            int p = tid + i*256;
            int r = p >> 2, kq = (p & 3) * 4;
            float4 va = *(const float4*)&A[(size_t)(row0 + r)*D + k0 + kq];
            As[kq+0][r] = va.x; As[kq+1][r] = va.y;
            As[kq+2][r] = va.z; As[kq+3][r] = va.w;
        }
        {
            int r = tid >> 4, cq = (tid & 15) * 4;
            *(float4*)&Bs[r][cq] = *(const float4*)&W[(size_t)(k0 + r)*HA + cq];
        }
        __syncthreads();
#pragma unroll
        for (int kk = 0; kk < 16; kk++) {
            float4 a0 = *(const float4*)&As[kk][ty*8];
            float4 a1 = *(const float4*)&As[kk][ty*8+4];
            float4 b0 = *(const float4*)&Bs[kk][tx*4];
            float a[8] = {a0.x,a0.y,a0.z,a0.w,a1.x,a1.y,a1.z,a1.w};
            float bb[4] = {b0.x,b0.y,b0.z,b0.w};
#pragma unroll
            for (int i = 0; i < 8; i++)
#pragma unroll
                for (int j = 0; j < 4; j++)
                    acc[i][j] += a[i]*bb[j];
        }
        __syncthreads();
    }
#pragma unroll
    for (int i = 0; i < 8; i++) {
        size_t r = row0 + ty*8 + i;
#pragma unroll
        for (int j = 0; j < 4; j++)
            C[r*HA + tx*4 + j] = acc[i][j];
    }
}

// ---------------- big GEMM: 128x128 tile, 8x8 microtile ------------------------
#define GM 128
#define GN 128
#define GK 16

__global__ void __launch_bounds__(256, 2)
gemm128_kernel(const float* __restrict__ A,
               const float* __restrict__ W,
               const float* __restrict__ bias,
               const float* __restrict__ resid,
               float* __restrict__ C,
               int M, int N, int K)
{
    __shared__ float As[GK][GM+4];   // pitch 132
    __shared__ float Bs[GK][GN];
    int tid = threadIdx.x;
    int row0 = blockIdx.y * GM;
    int col0 = blockIdx.x * GN;
    int tx = tid & 15, ty = tid >> 4;
    float acc[8][8] = {};
    for (int k0 = 0; k0 < K; k0 += GK) {
#pragma unroll
        for (int i = 0; i < 2; i++) {
            int p = tid + i*256;          // 0..511
            int r = p >> 2, kq = (p & 3) * 4;
            float4 va = *(const float4*)&A[(size_t)(row0 + r)*K + k0 + kq];
            As[kq+0][r] = va.x; As[kq+1][r] = va.y;
            As[kq+2][r] = va.z; As[kq+3][r] = va.w;
        }
#pragma unroll
        for (int i = 0; i < 2; i++) {
            int p = tid + i*256;
            int r = p >> 5, cq = (p & 31) * 4;
            *(float4*)&Bs[r][cq] = *(const float4*)&W[(size_t)(k0 + r)*N + col0 + cq];
        }
        __syncthreads();
#pragma unroll
        for (int kk = 0; kk < GK; kk++) {
            float4 a0 = *(const float4*)&As[kk][ty*8];
            float4 a1 = *(const float4*)&As[kk][ty*8+4];
            float4 b0 = *(const float4*)&Bs[kk][tx*8];
            float4 b1 = *(const float4*)&Bs[kk][tx*8+4];
            float a[8] = {a0.x,a0.y,a0.z,a0.w,a1.x,a1.y,a1.z,a1.w};
            float bb[8] = {b0.x,b0.y,b0.z,b0.w,b1.x,b1.y,b1.z,b1.w};
#pragma unroll
            for (int i = 0; i < 8; i++)
#pragma unroll
                for (int j = 0; j < 8; j++)
                    acc[i][j] += a[i]*bb[j];
        }
        __syncthreads();
    }
#pragma unroll
    for (int i = 0; i < 8; i++) {
        size_t r = row0 + ty*8 + i;
#pragma unroll
        for (int j = 0; j < 8; j++) {
            int c = col0 + tx*8 + j;
            float v = acc[i][j];
            if (bias)  v += bias[c];
            if (resid) v += resid[r*(size_t)N + c];
            C[r*(size_t)N + c] = v;
        }
    }
}

// ---- hattn = relu(bn_pos(hp)) @ Wp2a + ka[gather] - qa + cvec  ([M,64]) ------
__global__ void __launch_bounds__(256)
hattn_kernel()
{
    __shared__ float Aw[64][65];
    __shared__ float Bw[64*64];
    int tid = threadIdx.x;
    int m0 = blockIdx.x * 64;
#pragma unroll
    for (int i = 0; i < 16; i++) {
        int idx = tid + i*256;
        int r = idx >> 6, k = idx & 63;
        float h = g_hpos[(size_t)(m0+r)*64 + k];
        Aw[r][k] = fmaxf(h*g_stats[256+k] + g_stats[320+k], 0.0f);
        Bw[idx] = g_Wp2a[idx];
    }
    __syncthreads();
    int tx = tid & 15, ty = tid >> 4;
    float acc[4][4] = {};
#pragma unroll 4
    for (int kk = 0; kk < 64; kk++) {
        float a[4], bb[4];
#pragma unroll
        for (int i = 0; i < 4; i++) a[i] = Aw[ty*4+i][kk];
#pragma unroll
        for (int j = 0; j < 4; j++) bb[j] = Bw[kk*64 + tx*4 + j];
#pragma unroll
        for (int i = 0; i < 4; i++)
#pragma unroll
            for (int j = 0; j < 4; j++)
                acc[i][j] += a[i]*bb[j];
    }
#pragma unroll
    for (int i = 0; i < 4; i++) {
        int m = m0 + ty*4 + i;
        int b = m >> 15;
        int n = (m >> 4) & 2047;
        int jj = g_nidx[m];
        const float* kar = &g_ka[(((size_t)b<<11) + jj)*HA];
        const float* qar = &g_qa[(((size_t)b<<11) + n )*HA];
#pragma unroll
        for (int j = 0; j < 4; j++) {
            int c = tx*4 + j;
            g_hattn[(size_t)m*HA + c] = acc[i][j] + kar[c] - qar[c] + g_cvec[c];
        }
    }
}

// ---- fused: attn GEMM + pos GEMM (merged k-loop) + softmax(K) + agg -> g_x ---
// block: 64 rows (4 queries x 16 neighbors) x 128 cols; grid (2, 2048)
__global__ void __launch_bounds__(256)
attnout_kernel(const float* __restrict__ Wa2,
               const float* __restrict__ ba2,
               const float* __restrict__ Wp2,
               const float* __restrict__ bp2)
{
    extern __shared__ float sm[];
    float* Ah     = sm;                 // [64][65]
    float* Ap     = Ah + 64*65;         // [64][65]
    float* attn_s = Ap + 64*65;         // [64][132]
    float* pos_s  = attn_s + 64*132;    // [64][132]
    float* BsA    = pos_s + 64*132;     // [16][128]
    float* BsP    = BsA + 16*128;       // [16][128]
    int*   sj     = (int*)(BsP + 16*128);// [64]

    int tid = threadIdx.x;
    int m0 = blockIdx.y * 64;
    int c0 = blockIdx.x * 128;
    int tx = tid & 15, ty = tid >> 4;

#pragma unroll
    for (int i = 0; i < 16; i++) {
        int idx = tid + i*256;
        int r = idx >> 6, k = idx & 63;
        float ha = g_hattn[(size_t)(m0+r)*64 + k];
        Ah[r*65 + k] = fmaxf(ha*g_stats[384+k] + g_stats[448+k], 0.0f);
        float hp = g_hpos[(size_t)(m0+r)*64 + k];
        Ap[r*65 + k] = fmaxf(hp*g_stats[256+k] + g_stats[320+k], 0.0f);
    }
    if (tid < 64) sj[tid] = g_nidx[m0 + tid];

    float accA[4][8] = {};
    float accP[4][8] = {};
    for (int k0 = 0; k0 < 64; k0 += 16) {
        __syncthreads();
#pragma unroll
        for (int i = 0; i < 2; i++) {
            int p = tid + i*256;
            int r = p >> 5, cq = (p & 31)*4;
            *(float4*)&BsA[r*128 + cq] = *(const float4*)&Wa2[(size_t)(k0+r)*D + c0 + cq];
            *(float4*)&BsP[r*128 + cq] = *(const float4*)&Wp2[(size_t)(k0+r)*D + c0 + cq];
        }
        __syncthreads();
#pragma unroll
        for (int kk = 0; kk < 16; kk++) {
            float ah[4], ap[4];
#pragma unroll
            for (int i = 0; i < 4; i++) {
                ah[i] = Ah[(ty*4+i)*65 + k0 + kk];
                ap[i] = Ap[(ty*4+i)*65 + k0 + kk];
            }
            float4 a0 = *(const float4*)&BsA[kk*128 + tx*8];
            float4 a1 = *(const float4*)&BsA[kk*128 + tx*8 + 4];
            float4 p0 = *(const float4*)&BsP[kk*128 + tx*8];
            float4 p1 = *(const float4*)&BsP[kk*128 + tx*8 + 4];
            float ba[8] = {a0.x,a0.y,a0.z,a0.w,a1.x,a1.y,a1.z,a1.w};
            float bp[8] = {p0.x,p0.y,p0.z,p0.w,p1.x,p1.y,p1.z,p1.w};
#pragma unroll
            for (int i = 0; i < 4; i++)
#pragma unroll
                for (int j = 0; j < 8; j++) {
                    accA[i][j] += ah[i]*ba[j];
                    accP[i][j] += ap[i]*bp[j];
                }
        }
    }
    __syncthreads();
#pragma unroll
    for (int i = 0; i < 4; i++)
#pragma unroll
        for (int j = 0; j < 8; j++) {
            attn_s[(ty*4+i)*132 + tx*8 + j] = accA[i][j] + ba2[c0 + tx*8 + j];
            pos_s [(ty*4+i)*132 + tx*8 + j] = accP[i][j] + bp2[c0 + tx*8 + j];
        }
    __syncthreads();

    // ---- softmax over 16 neighbors + aggregation
#pragma unroll
    for (int e = tid; e < 512; e += 256) {
        int q = e >> 7;            // 0..3
        int c = e & 127;
        int mrow = q*16;
        float mx = -1e30f;
#pragma unroll
        for (int k = 0; k < KNN; k++)
            mx = fmaxf(mx, attn_s[(mrow+k)*132 + c]);
        float w[KNN]; float s = 0.f;
#pragma unroll
        for (int k = 0; k < KNN; k++) {
            w[k] = __expf(attn_s[(mrow+k)*132 + c] - mx);
            s += w[k];
        }
        float inv = 1.0f / s;
        int qg = (m0 >> 4) + q;
        int b = qg >> 11;
        float x = 0.f;
#pragma unroll
        for (int k = 0; k < KNN; k++) {
            int j = sj[mrow + k];
            float vv = g_v[(((size_t)b<<11) + j)*D + c0 + c] + pos_s[(mrow+k)*132 + c];
            x += vv * w[k];
        }
        g_x[(size_t)qg*D + c0 + c] = x * inv;
    }
}

// =================================================================================
extern "C" void kernel_launch(void* const* d_in, const int* in_sizes, int n_in,
                              void* d_out, int out_size)
{
    const float* dec_x   = (const float*)d_in[0];
    const float* dec_pc  = (const float*)d_in[1];
    const float* enc_x   = (const float*)d_in[2];
    const float* enc_pc  = (const float*)d_in[3];
    const float* W_pre1  = (const float*)d_in[4];
    const float* b_pre1  = (const float*)d_in[5];
    const float* W_pre2  = (const float*)d_in[6];
    const float* b_pre2  = (const float*)d_in[7];
    const float* Wq      = (const float*)d_in[8];
    const float* bq      = (const float*)d_in[9];
    const float* Wk      = (const float*)d_in[10];
    const float* bk      = (const float*)d_in[11];
    const float* Wv      = (const float*)d_in[12];
    const float* bv      = (const float*)d_in[13];
    const float* Wp1     = (const float*)d_in[14];
    const float* bp1     = (const float*)d_in[15];
    const float* gp      = (const float*)d_in[16];
    const float* betap   = (const float*)d_in[17];
    const float* Wp2     = (const float*)d_in[18];
    const float* bp2     = (const float*)d_in[19];
    const float* Wa1     = (const float*)d_in[20];
    const float* ba1     = (const float*)d_in[21];
    const float* ga      = (const float*)d_in[22];
    const float* betaa   = (const float*)d_in[23];
    const float* Wa2     = (const float*)d_in[24];
    const float* ba2     = (const float*)d_in[25];
    const float* W_post1 = (const float*)d_in[26];
    const float* b_post1 = (const float*)d_in[27];
    const float* W_post2 = (const float*)d_in[28];
    const float* b_post2 = (const float*)d_in[29];
    float* out = (float*)d_out;

    float *p_dx, *p_ex, *p_sx, *p_qa, *p_ka, *p_v, *p_hpos, *p_hattn, *p_x;
    float *p_WkWa1, *p_WqWa1, *p_Wp2a, *p_stats;
    cudaGetSymbolAddress((void**)&p_dx,    g_dx);
    cudaGetSymbolAddress((void**)&p_ex,    g_ex);
    cudaGetSymbolAddress((void**)&p_sx,    g_sx);
    cudaGetSymbolAddress((void**)&p_qa,    g_qa);
    cudaGetSymbolAddress((void**)&p_ka,    g_ka);
    cudaGetSymbolAddress((void**)&p_v,     g_v);
    cudaGetSymbolAddress((void**)&p_hpos,  g_hpos);
    cudaGetSymbolAddress((void**)&p_hattn, g_hattn);
    cudaGetSymbolAddress((void**)&p_x,     g_x);
    cudaGetSymbolAddress((void**)&p_WkWa1, g_WkWa1);
    cudaGetSymbolAddress((void**)&p_WqWa1, g_WqWa1);
    cudaGetSymbolAddress((void**)&p_Wp2a,  g_Wp2a);
    cudaGetSymbolAddress((void**)&p_stats, g_stats);

    const int M8 = B*N1;                         // 8192
    dim3 g128(D/GN, M8/GM);                      // (2,64)

    // 0) weight precomputes + constants
    gemm_bias_kernel<<<dim3(1, 4), 256>>>(Wk,  Wa1, nullptr, nullptr, p_WkWa1, D,  HA, D);
    gemm_bias_kernel<<<dim3(1, 4), 256>>>(Wq,  Wa1, nullptr, nullptr, p_WqWa1, D,  HA, D);
    gemm_bias_kernel<<<dim3(1, 1), 256>>>(Wp2, Wa1, nullptr, nullptr, p_Wp2a,  HP, HA, D);
    cvec_kernel<<<1, 256>>>(bk, bq, bp2, Wa1, ba1);
    zero_stats_kernel<<<1, 256>>>();

    // 1) pre-projections
    gemm128_kernel<<<g128, 256>>>(dec_x, W_pre1, b_pre1, nullptr, p_dx, M8, D, D);
    gemm128_kernel<<<g128, 256>>>(enc_x, W_pre2, b_pre2, nullptr, p_ex, M8, D, D);

    // 2) FPS
    cudaFuncSetAttribute(fps_kernel, cudaFuncAttributeMaxDynamicSharedMemorySize, 3*NC*sizeof(float));
    fps_kernel<<<B, 512, 3*NC*sizeof(float)>>>(dec_pc, enc_pc);

    // 3) gather sampled features + coords
    gather_kernel<<<M8/4, 256>>>(dec_pc, enc_pc);

    // 4) qa/ka (one fused launch) + v
    gemm_n64_kernel<<<dim3(2, M8/128), 256>>>(p_dx, p_sx, p_WqWa1, p_WkWa1, p_qa, p_ka);
    gemm128_kernel<<<g128, 256>>>(p_sx, Wv, bv, nullptr, p_v, M8, D, D);

    // 5) KNN
    knn_kernel<<<dim3(N1/256, B), 256>>>(dec_pc);

    // 6) pos branch hidden + BN stats
    hpos_kernel<<<MROW/4, 256>>>(dec_pc, Wp1, bp1);
    colstats_kernel<<<256, 256>>>(p_hpos, MROW, p_stats + 0, p_stats + 64);
    finalize_bn_kernel<<<1, 64>>>(p_stats + 0, p_stats + 64, gp, betap,
                                  1.0f/(float)MROW, p_stats + 256, p_stats + 320);

    // 7) hattn compose + BN stats
    hattn_kernel<<<MROW/64, 256>>>();
    colstats_kernel<<<256, 256>>>(p_hattn, MROW, p_stats + 128, p_stats + 192);
    finalize_bn_kernel<<<1, 64>>>(p_stats + 128, p_stats + 192, ga, betaa,
                                  1.0f/(float)MROW, p_stats + 384, p_stats + 448);

    // 8) fused attn/pos GEMMs + softmax + aggregation
    cudaFuncSetAttribute(attnout_kernel, cudaFuncAttributeMaxDynamicSharedMemorySize, 124*1024);
    size_t smbytes = (size_t)(64*65*2 + 64*132*2 + 2*16*128)*sizeof(float) + 64*sizeof(int);
    attnout_kernel<<<dim3(2, MROW/64), 256, smbytes>>>(Wa2, ba2, Wp2, bp2);

    // 9) outputs
    float* out1 = out;                                   // [B,N1,256]
    float* opc1 = out + (size_t)M8*D;                    // [B,N1,3]
    float* out2 = opc1 + (size_t)M8*3;                   // [B,N1,256]
    float* opc2 = out2 + (size_t)M8*D;                   // [B,N2,3]
    gemm128_kernel<<<g128, 256>>>(p_x, W_post1, b_post1, dec_x, out1, M8, D, D);
    gemm128_kernel<<<g128, 256>>>(p_x, W_post2, b_post2, nullptr, out2, M8, D, D);
    cudaMemcpyAsync(opc1, dec_pc, (size_t)M8*3*sizeof(float), cudaMemcpyDeviceToDevice);
    cudaMemcpyAsync(opc2, enc_pc, (size_t)B*N2*3*sizeof(float), cudaMemcpyDeviceToDevice);
}

// round 6
// speedup vs baseline: 1.3925x; 1.0662x over previous
#include <cuda_runtime.h>
#include <cuda_bf16.h>
#include <math.h>
#include <stdint.h>

// Problem constants
#define B    4
#define N1   2048
#define N2   2048
#define NC   4096           // N1+N2
#define D    256
#define HP   64
#define HA   64
#define KNN  16
#define MROW (B*N1*KNN)     // 131072

// ---------------- scratch (device globals; no allocation allowed) -------------
__device__ float g_dx  [B*N1*D];
__device__ float g_ex  [B*N2*D];
__device__ float g_sx  [B*N1*D];
__device__ float g_spc [B*N1*3];
__device__ int   g_fidx[B*N1];
__device__ float g_qa  [B*N1*HA];
__device__ float g_ka  [B*N1*HA];
__device__ float g_v   [B*N1*D];
__device__ int   g_nidx[B*N1*KNN];
__device__ float g_hpos [MROW*HP];
__device__ float g_hattn[MROW*HA];
__device__ float g_x   [B*N1*D];
__device__ float g_WkWa1[D*HA];
__device__ float g_WqWa1[D*HA];
__device__ float g_Wp2a [HP*HA];
__device__ float g_cvec [HA];
// [0:64) psum [64:128) psq [128:192) asum [192:256) asq
// [256:320) pscale [320:384) pshift [384:448) ascale [448:512) ashift
__device__ float g_stats[512];

// ================= tf32 mma helpers ===========================================
__device__ __forceinline__ uint32_t f2tf(float x) {
    uint32_t r; asm("cvt.rna.tf32.f32 %0, %1;" : "=r"(r) : "f"(x)); return r;
}
__device__ __forceinline__ void mma8(float* d, const uint32_t* a, const uint32_t* b) {
    asm volatile("mma.sync.aligned.m16n8k8.row.col.f32.tf32.tf32.f32 "
        "{%0,%1,%2,%3}, {%4,%5,%6,%7}, {%8,%9}, {%0,%1,%2,%3};"
        : "+f"(d[0]), "+f"(d[1]), "+f"(d[2]), "+f"(d[3])
        : "r"(a[0]), "r"(a[1]), "r"(a[2]), "r"(a[3]), "r"(b[0]), "r"(b[1]));
}

// ---------------- tf32 GEMM body: 128x128 tile, 512 threads, warp tile 32x32 ---
#define APITCH 36
#define BPITCH 136
__device__ __forceinline__ void gemm_tf32_body(
    const float* __restrict__ A, const float* __restrict__ W,
    const float* __restrict__ bias, const float* __restrict__ resid,
    float* __restrict__ C, int bx, int by, int N, int K)
{
    extern __shared__ float smext[];
    float* As = smext;                 // [128][36] tf32 bits
    float* Bs = smext + 128*APITCH;    // [32][136]
    int tid = threadIdx.x;
    int row0 = by * 128, col0 = bx * 128;
    int warp = tid >> 5, lane = tid & 31;
    int mw = (warp & 3) * 32, nw = (warp >> 2) * 32;
    int g = lane >> 2, tg = lane & 3;
    float acc[8][4] = {};
    for (int k0 = 0; k0 < K; k0 += 32) {
#pragma unroll
        for (int i = 0; i < 2; i++) {
            int idx = tid + i*512;
            int r = idx >> 3, c4 = (idx & 7) * 4;
            float4 v = *(const float4*)&A[(size_t)(row0+r)*K + k0 + c4];
            As[r*APITCH + c4+0] = __uint_as_float(f2tf(v.x));
            As[r*APITCH + c4+1] = __uint_as_float(f2tf(v.y));
            As[r*APITCH + c4+2] = __uint_as_float(f2tf(v.z));
            As[r*APITCH + c4+3] = __uint_as_float(f2tf(v.w));
        }
#pragma unroll
        for (int i = 0; i < 2; i++) {
            int idx = tid + i*512;
            int r = idx >> 5, c4 = (idx & 31) * 4;
            float4 v = *(const float4*)&W[(size_t)(k0+r)*N + col0 + c4];
            Bs[r*BPITCH + c4+0] = __uint_as_float(f2tf(v.x));
            Bs[r*BPITCH + c4+1] = __uint_as_float(f2tf(v.y));
            Bs[r*BPITCH + c4+2] = __uint_as_float(f2tf(v.z));
            Bs[r*BPITCH + c4+3] = __uint_as_float(f2tf(v.w));
        }
        __syncthreads();
#pragma unroll
        for (int ks = 0; ks < 32; ks += 8) {
            uint32_t af[2][4], bf[4][2];
#pragma unroll
            for (int mi = 0; mi < 2; mi++) {
                int rb = mw + mi*16;
                af[mi][0] = __float_as_uint(As[(rb+g  )*APITCH + ks+tg  ]);
                af[mi][1] = __float_as_uint(As[(rb+g+8)*APITCH + ks+tg  ]);
                af[mi][2] = __float_as_uint(As[(rb+g  )*APITCH + ks+tg+4]);
                af[mi][3] = __float_as_uint(As[(rb+g+8)*APITCH + ks+tg+4]);
            }
#pragma unroll
            for (int ni = 0; ni < 4; ni++) {
                bf[ni][0] = __float_as_uint(Bs[(ks+tg  )*BPITCH + nw + ni*8 + g]);
                bf[ni][1] = __float_as_uint(Bs[(ks+tg+4)*BPITCH + nw + ni*8 + g]);
            }
#pragma unroll
            for (int mi = 0; mi < 2; mi++)
#pragma unroll
                for (int ni = 0; ni < 4; ni++)
                    mma8(acc[mi*4+ni], af[mi], bf[ni]);
        }
        __syncthreads();
    }
#pragma unroll
    for (int mi = 0; mi < 2; mi++) {
#pragma unroll
        for (int ni = 0; ni < 4; ni++) {
            int c = col0 + nw + ni*8 + 2*tg;
            float b0 = bias ? bias[c]   : 0.f;
            float b1 = bias ? bias[c+1] : 0.f;
            size_t r1 = (size_t)(row0 + mw + mi*16 + g);
            size_t r2 = r1 + 8;
            float v00 = acc[mi*4+ni][0] + b0, v01 = acc[mi*4+ni][1] + b1;
            float v10 = acc[mi*4+ni][2] + b0, v11 = acc[mi*4+ni][3] + b1;
            if (resid) {
                v00 += resid[r1*N+c]; v01 += resid[r1*N+c+1];
                v10 += resid[r2*N+c]; v11 += resid[r2*N+c+1];
            }
            *(float2*)&C[r1*N + c] = make_float2(v00, v01);
            *(float2*)&C[r2*N + c] = make_float2(v10, v11);
        }
    }
}

__global__ void __launch_bounds__(512)
gemm_tf32_kernel(const float* __restrict__ A, const float* __restrict__ W,
                 const float* __restrict__ bias, const float* __restrict__ resid,
                 float* __restrict__ C, int N, int K)
{
    gemm_tf32_body(A, W, bias, resid, C, blockIdx.x, blockIdx.y, N, K);
}

// ---------------- FPS body: 512 threads, one barrier per iteration -------------
__device__ void fps_body(int b, const float* __restrict__ decpc,
                         const float* __restrict__ encpc)
{
    extern __shared__ float smext[];
    float* sx = smext;
    float* sy = smext + NC;
    float* sz = smext + 2*NC;
    __shared__ unsigned long long swk[2][16];

    int tid = threadIdx.x;
    int wid = tid >> 5, lid = tid & 31;

    for (int j = tid; j < N1; j += 512) {
        sx[j] = decpc[((size_t)b*N1 + j)*3 + 0];
        sy[j] = decpc[((size_t)b*N1 + j)*3 + 1];
        sz[j] = decpc[((size_t)b*N1 + j)*3 + 2];
        sx[N1+j] = encpc[((size_t)b*N2 + j)*3 + 0];
        sy[N1+j] = encpc[((size_t)b*N2 + j)*3 + 1];
        sz[N1+j] = encpc[((size_t)b*N2 + j)*3 + 2];
    }
    float md[8];
#pragma unroll
    for (int t = 0; t < 8; t++) md[t] = 1e10f;
    if (tid == 0) g_fidx[b*N1] = 0;
    int cur = 0;
    __syncthreads();

    for (int i = 1; i < N1; i++) {
        float lx = sx[cur], ly = sy[cur], lz = sz[cur];
        float bestv = -1.0f; int besti = 0x7fffffff;
#pragma unroll
        for (int t = 0; t < 8; t++) {
            int j = tid + t*512;
            float ddx = sx[j]-lx, ddy = sy[j]-ly, ddz = sz[j]-lz;
            float d = ddx*ddx + ddy*ddy + ddz*ddz;
            float mm = fminf(md[t], d);
            md[t] = mm;
            if (mm > bestv) { bestv = mm; besti = j; }
        }
        unsigned kb = __float_as_uint(bestv);
        kb = ((int)kb < 0) ? ~kb : (kb | 0x80000000u);
        unsigned mk;
        asm("redux.sync.max.u32 %0, %1, 0xffffffff;" : "=r"(mk) : "r"(kb));
        unsigned idxc = (kb == mk) ? (unsigned)besti : 0xffffffffu;
        unsigned mi;
        asm("redux.sync.min.u32 %0, %1, 0xffffffff;" : "=r"(mi) : "r"(idxc));
        int pb = i & 1;
        if (lid == 0)
            swk[pb][wid] = (((unsigned long long)mk) << 32) | (unsigned long long)(0xffffffffu - mi);
        __syncthreads();
        unsigned long long best = swk[pb][0];
#pragma unroll
        for (int w = 1; w < 16; w++) {
            unsigned long long o = swk[pb][w];
            best = (o > best) ? o : best;
        }
        cur = (int)(0xffffffffu - (unsigned)best);
        if (tid == 0) g_fidx[b*N1 + i] = cur;
    }
}

// ---------------- small 64-col GEMM body (weight precomputes), 512 thr --------
#define TBM 64
#define TBK 16
__device__ void gemm64_body(const float* __restrict__ A, const float* __restrict__ W,
                            float* __restrict__ C, int row0, int N, int K)
{
    __shared__ float As64[TBK][TBM];
    __shared__ float Bs64[TBK][64];
    int tid = threadIdx.x;
    for (int k0 = 0; k0 < K; k0 += TBK) {
#pragma unroll
        for (int u = 0; u < 2; u++) {
            int e = tid + u*512;
            int r = e >> 4, c = e & 15;
            As64[c][r] = A[(size_t)(row0 + r)*K + k0 + c];
            int r2 = e >> 6, c2 = e & 63;
            Bs64[r2][c2] = W[(size_t)(k0 + r2)*N + c2];
        }
        __syncthreads();
        if (tid < 256) {
            int tx = tid & 15, ty = tid >> 4;
            float acc[4][4] = {};
#pragma unroll
            for (int kk = 0; kk < TBK; kk++) {
                float a[4], bb[4];
#pragma unroll
                for (int i = 0; i < 4; i++) a[i] = As64[kk][ty*4+i];
#pragma unroll
                for (int j = 0; j < 4; j++) bb[j] = Bs64[kk][tx*4+j];
#pragma unroll
                for (int i = 0; i < 4; i++)
#pragma unroll
                    for (int j = 0; j < 4; j++)
                        acc[i][j] += a[i]*bb[j];
            }
            // accumulate into C across chunks via registers would need persistence;
            // instead accumulate in global: first chunk writes, rest adds
#pragma unroll
            for (int i = 0; i < 4; i++)
#pragma unroll
                for (int j = 0; j < 4; j++) {
                    size_t off = (size_t)(row0 + ty*4 + i)*N + tx*4 + j;
                    if (k0 == 0) C[off] = acc[i][j];
                    else         C[off] += acc[i][j];
                }
        }
        __syncthreads();
    }
}

// ---------------- cvec body: (bk - bq + bp2) @ Wa1 + ba1, 512 thr --------------
__device__ void cvec_body(const float* __restrict__ bk, const float* __restrict__ bq,
                          const float* __restrict__ bp2, const float* __restrict__ Wa1,
                          const float* __restrict__ ba1)
{
    __shared__ float shc[512];
    int c = threadIdx.x & 63;
    int part = threadIdx.x >> 6;     // 0..7
    float s = 0.f;
    for (int i = part*32; i < part*32 + 32; i++)
        s += (bk[i] - bq[i] + bp2[i]) * Wa1[(size_t)i*HA + c];
    shc[threadIdx.x] = s;
    __syncthreads();
    if (part == 0) {
        float t = ba1[c];
#pragma unroll
        for (int p = 0; p < 8; p++) t += shc[p*64 + c];
        g_cvec[c] = t;
    }
}

// ---------------- phase-1 mega-kernel -----------------------------------------
// blocks: [0,4)=FPS  [4,132)=pre1 gemm  [132,260)=pre2 gemm
//         [260,264)=WkWa1 [264,268)=WqWa1 [268]=Wp2a [269]=cvec [270]=zero_stats
__global__ void __launch_bounds__(512)
phase1_kernel(const float* __restrict__ dec_pc, const float* __restrict__ enc_pc,
              const float* __restrict__ dec_x,  const float* __restrict__ enc_x,
              const float* __restrict__ W_pre1, const float* __restrict__ b_pre1,
              const float* __restrict__ W_pre2, const float* __restrict__ b_pre2,
              const float* __restrict__ Wk, const float* __restrict__ Wq,
              const float* __restrict__ Wa1, const float* __restrict__ Wp2,
              const float* __restrict__ bk, const float* __restrict__ bq,
              const float* __restrict__ bp2, const float* __restrict__ ba1)
{
    int bid = blockIdx.x;
    if (bid < 4) {
        fps_body(bid, dec_pc, enc_pc);
    } else if (bid < 132) {
        int t = bid - 4;
        gemm_tf32_body(dec_x, W_pre1, b_pre1, nullptr, g_dx, t & 1, t >> 1, D, D);
    } else if (bid < 260) {
        int t = bid - 132;
        gemm_tf32_body(enc_x, W_pre2, b_pre2, nullptr, g_ex, t & 1, t >> 1, D, D);
    } else if (bid < 264) {
        gemm64_body(Wk, Wa1, g_WkWa1, (bid-260)*64, HA, D);
    } else if (bid < 268) {
        gemm64_body(Wq, Wa1, g_WqWa1, (bid-264)*64, HA, D);
    } else if (bid == 268) {
        gemm64_body(Wp2, Wa1, g_Wp2a, 0, HA, D);
    } else if (bid == 269) {
        cvec_body(bk, bq, bp2, Wa1, ba1);
    } else {
        g_stats[threadIdx.x] = 0.0f;
    }
}

// ---------------- gather sampled features + coords ----------------------------
__global__ void gather_kernel(const float* __restrict__ decpc,
                              const float* __restrict__ encpc)
{
    int row = blockIdx.x*4 + (threadIdx.x >> 6);
    int c4  = (threadIdx.x & 63) * 4;
    int b = row >> 11;
    int j = g_fidx[row];
    const float* src = (j < N1) ? &g_dx[((size_t)b*N1 + j)*D]
                                : &g_ex[((size_t)b*N2 + (j - N1))*D];
    *(float4*)&g_sx[(size_t)row*D + c4] = *(const float4*)&src[c4];
    if ((threadIdx.x & 63) < 3) {
        int cc = threadIdx.x & 63;
        const float* ps = (j < N1) ? &decpc[((size_t)b*N1 + j)*3]
                                   : &encpc[((size_t)b*N2 + (j - N1))*3];
        g_spc[(size_t)row*3 + cc] = ps[cc];
    }
}

// ---------------- KNN: one thread per query -----------------------------------
__global__ void knn_kernel(const float* __restrict__ decpc)
{
    __shared__ float px[N1], py[N1], pz[N1], s2s[N1];
    int b = blockIdx.y;
    int tid = threadIdx.x;
    for (int m = tid; m < N1; m += 256) {
        float x = g_spc[((size_t)b*N1 + m)*3 + 0];
        float y = g_spc[((size_t)b*N1 + m)*3 + 1];
        float z = g_spc[((size_t)b*N1 + m)*3 + 2];
        px[m] = x; py[m] = y; pz[m] = z;
        s2s[m] = x*x + y*y + z*z;
    }
    __syncthreads();
    int q = blockIdx.x*256 + tid;
    float qx = decpc[((size_t)b*N1 + q)*3 + 0];
    float qy = decpc[((size_t)b*N1 + q)*3 + 1];
    float qz = decpc[((size_t)b*N1 + q)*3 + 2];
    float s1 = qx*qx + qy*qy + qz*qz;
    float bd[KNN]; int bi[KNN];
#pragma unroll
    for (int t = 0; t < KNN; t++) { bd[t] = 1e30f; bi[t] = 0; }
    for (int m = 0; m < N1; m++) {
        float d = s1 + s2s[m] - 2.0f*(qx*px[m] + qy*py[m] + qz*pz[m]);
        if (d < bd[KNN-1]) {
            bd[KNN-1] = d; bi[KNN-1] = m;
#pragma unroll
            for (int t = KNN-1; t > 0; t--) {
                if (bd[t] < bd[t-1]) {
                    float td = bd[t]; bd[t] = bd[t-1]; bd[t-1] = td;
                    int   ti = bi[t]; bi[t] = bi[t-1]; bi[t-1] = ti;
                }
            }
        }
    }
#pragma unroll
    for (int t = 0; t < KNN; t++)
        g_nidx[((size_t)b*N1 + q)*KNN + t] = bi[t];
}

// ---------------- hpos: pos_in @ Wp1 + bp1 ------------------------------------
__global__ void hpos_kernel(const float* __restrict__ decpc,
                            const float* __restrict__ Wp1,
                            const float* __restrict__ bp1)
{
    int m = blockIdx.x*4 + (threadIdx.x >> 6);
    int c = threadIdx.x & 63;
    int b = m >> 15;
    int n = (m >> 4) & 2047;
    int j = g_nidx[m];
    const float* pp = &g_spc[((size_t)b*N1 + j)*3];
    const float* qq = &decpc[((size_t)b*N1 + n)*3];
    float p0 = pp[0]-qq[0], p1 = pp[1]-qq[1], p2 = pp[2]-qq[2];
    float h = p0*Wp1[c] + p1*Wp1[64+c] + p2*Wp1[128+c] + bp1[c];
    g_hpos[(size_t)m*HP + c] = h;
}

// ---------------- column stats over [M,64] matrix ------------------------------
__global__ void colstats_kernel(const float* __restrict__ X, int M,
                                float* __restrict__ sum, float* __restrict__ sumsq)
{
    int c  = threadIdx.x & 63;
    int rg = threadIdx.x >> 6;
    float s = 0.f, s2 = 0.f;
    for (int r = blockIdx.x*4 + rg; r < M; r += gridDim.x*4) {
        float v = X[(size_t)r*64 + c];
        s += v; s2 += v*v;
    }
    __shared__ float sh[256], sh2[256];
    sh[threadIdx.x] = s; sh2[threadIdx.x] = s2;
    __syncthreads();
    if (rg == 0) {
        s  = sh[c]  + sh[64+c]  + sh[128+c]  + sh[192+c];
        s2 = sh2[c] + sh2[64+c] + sh2[128+c] + sh2[192+c];
        atomicAdd(&sum[c], s);
        atomicAdd(&sumsq[c], s2);
    }
}

__global__ void finalize_bn_kernel(const float* __restrict__ sum,
                                   const float* __restrict__ sumsq,
                                   const float* __restrict__ g,
                                   const float* __restrict__ beta,
                                   float invM,
                                   float* __restrict__ scale,
                                   float* __restrict__ shift)
{
    int c = threadIdx.x;
    float mean = sum[c]*invM;
    float var  = sumsq[c]*invM - mean*mean;
    float sc = g[c]*rsqrtf(var + 1e-5f);
    scale[c] = sc;
    shift[c] = beta[c] - mean*sc;
}

// ---------------- N=64 GEMM: 128x64 tile, 8x4 microtile (qa & ka in one) ------
__global__ void __launch_bounds__(256, 2)
gemm_n64_kernel(const float* __restrict__ A0, const float* __restrict__ A1,
                const float* __restrict__ W0, const float* __restrict__ W1,
                float* __restrict__ C0, float* __restrict__ C1)
{
    const float* A = blockIdx.x ? A1 : A0;
    const float* W = blockIdx.x ? W1 : W0;
    float*       C = blockIdx.x ? C1 : C0;
    __shared__ float As[16][132];
    __shared__ float Bs[16][64];
    int tid = threadIdx.x;
    int row0 = blockIdx.y * 128;
    int tx = tid & 15, ty = tid >> 4;
    float acc[8][4] = {};
    for (int k0 = 0; k0 < D; k0 += 16) {
#pragma unroll
        for (int i = 0; i < 2; i++) {
            int p = tid + i*256;
            int r = p >> 2, kq = (p & 3) * 4;
            float4 va = *(const float4*)&A[(size_t)(row0 + r)*D + k0 + kq];
            As[kq+0][r] = va.x; As[kq+1][r] = va.y;
            As[kq+2][r] = va.z; As[kq+3][r] = va.w;
        }
        {
            int r = tid >> 4, cq = (tid & 15) * 4;
            *(float4*)&Bs[r][cq] = *(const float4*)&W[(size_t)(k0 + r)*HA + cq];
        }
        __syncthreads();
#pragma unroll
        for (int kk = 0; kk < 16; kk++) {
            float4 a0 = *(const float4*)&As[kk][ty*8];
            float4 a1 = *(const float4*)&As[kk][ty*8+4];
            float4 b0 = *(const float4*)&Bs[kk][tx*4];
            float a[8] = {a0.x,a0.y,a0.z,a0.w,a1.x,a1.y,a1.z,a1.w};
            float bb[4] = {b0.x,b0.y,b0.z,b0.w};
#pragma unroll
            for (int i = 0; i < 8; i++)
#pragma unroll
                for (int j = 0; j < 4; j++)
                    acc[i][j] += a[i]*bb[j];
        }
        __syncthreads();
    }
#pragma unroll
    for (int i = 0; i < 8; i++) {
        size_t r = row0 + ty*8 + i;
#pragma unroll
        for (int j = 0; j < 4; j++)
            C[r*HA + tx*4 + j] = acc[i][j];
    }
}

// ---- hattn = relu(bn_pos(hp)) @ Wp2a + ka[gather] - qa + cvec  ([M,64]) ------
__global__ void __launch_bounds__(256)
hattn_kernel()
{
    __shared__ float Aw[64][65];
    __shared__ float Bw[64*64];
    int tid = threadIdx.x;
    int m0 = blockIdx.x * 64;
#pragma unroll
    for (int i = 0; i < 16; i++) {
        int idx = tid + i*256;
        int r = idx >> 6, k = idx & 63;
        float h = g_hpos[(size_t)(m0+r)*64 + k];
        Aw[r][k] = fmaxf(h*g_stats[256+k] + g_stats[320+k], 0.0f);
        Bw[idx] = g_Wp2a[idx];
    }
    __syncthreads();
    int tx = tid & 15, ty = tid >> 4;
    float acc[4][4] = {};
#pragma unroll 4
    for (int kk = 0; kk < 64; kk++) {
        float a[4], bb[4];
#pragma unroll
        for (int i = 0; i < 4; i++) a[i] = Aw[ty*4+i][kk];
#pragma unroll
        for (int j = 0; j < 4; j++) bb[j] = Bw[kk*64 + tx*4 + j];
#pragma unroll
        for (int i = 0; i < 4; i++)
#pragma unroll
            for (int j = 0; j < 4; j++)
                acc[i][j] += a[i]*bb[j];
    }
#pragma unroll
    for (int i = 0; i < 4; i++) {
        int m = m0 + ty*4 + i;
        int b = m >> 15;
        int n = (m >> 4) & 2047;
        int jj = g_nidx[m];
        const float* kar = &g_ka[(((size_t)b<<11) + jj)*HA];
        const float* qar = &g_qa[(((size_t)b<<11) + n )*HA];
#pragma unroll
        for (int j = 0; j < 4; j++) {
            int c = tx*4 + j;
            g_hattn[(size_t)m*HA + c] = acc[i][j] + kar[c] - qar[c] + g_cvec[c];
        }
    }
}

// ---- fused: attn GEMM + pos GEMM (merged k-loop) + softmax(K) + agg -> g_x ---
__global__ void __launch_bounds__(256)
attnout_kernel(const float* __restrict__ Wa2,
               const float* __restrict__ ba2,
               const float* __restrict__ Wp2,
               const float* __restrict__ bp2)
{
    extern __shared__ float sm[];
    float* Ah     = sm;                 // [64][65]
    float* Ap     = Ah + 64*65;         // [64][65]
    float* attn_s = Ap + 64*65;         // [64][132]
    float* pos_s  = attn_s + 64*132;    // [64][132]
    float* BsA    = pos_s + 64*132;     // [16][128]
    float* BsP    = BsA + 16*128;       // [16][128]
    int*   sj     = (int*)(BsP + 16*128);// [64]

    int tid = threadIdx.x;
    int m0 = blockIdx.y * 64;
    int c0 = blockIdx.x * 128;
    int tx = tid & 15, ty = tid >> 4;

#pragma unroll
    for (int i = 0; i < 16; i++) {
        int idx = tid + i*256;
        int r = idx >> 6, k = idx & 63;
        float ha = g_hattn[(size_t)(m0+r)*64 + k];
        Ah[r*65 + k] = fmaxf(ha*g_stats[384+k] + g_stats[448+k], 0.0f);
        float hp = g_hpos[(size_t)(m0+r)*64 + k];
        Ap[r*65 + k] = fmaxf(hp*g_stats[256+k] + g_stats[320+k], 0.0f);
    }
    if (tid < 64) sj[tid] = g_nidx[m0 + tid];

    float accA[4][8] = {};
    float accP[4][8] = {};
    for (int k0 = 0; k0 < 64; k0 += 16) {
        __syncthreads();
#pragma unroll
        for (int i = 0; i < 2; i++) {
            int p = tid + i*256;
            int r = p >> 5, cq = (p & 31)*4;
            *(float4*)&BsA[r*128 + cq] = *(const float4*)&Wa2[(size_t)(k0+r)*D + c0 + cq];
            *(float4*)&BsP[r*128 + cq] = *(const float4*)&Wp2[(size_t)(k0+r)*D + c0 + cq];
        }
        __syncthreads();
#pragma unroll
        for (int kk = 0; kk < 16; kk++) {
            float ah[4], ap[4];
#pragma unroll
            for (int i = 0; i < 4; i++) {
                ah[i] = Ah[(ty*4+i)*65 + k0 + kk];
                ap[i] = Ap[(ty*4+i)*65 + k0 + kk];
            }
            float4 a0 = *(const float4*)&BsA[kk*128 + tx*8];
            float4 a1 = *(const float4*)&BsA[kk*128 + tx*8 + 4];
            float4 p0 = *(const float4*)&BsP[kk*128 + tx*8];
            float4 p1 = *(const float4*)&BsP[kk*128 + tx*8 + 4];
            float ba[8] = {a0.x,a0.y,a0.z,a0.w,a1.x,a1.y,a1.z,a1.w};
            float bp[8] = {p0.x,p0.y,p0.z,p0.w,p1.x,p1.y,p1.z,p1.w};
#pragma unroll
            for (int i = 0; i < 4; i++)
#pragma unroll
                for (int j = 0; j < 8; j++) {
                    accA[i][j] += ah[i]*ba[j];
                    accP[i][j] += ap[i]*bp[j];
                }
        }
    }
    __syncthreads();
#pragma unroll
    for (int i = 0; i < 4; i++)
#pragma unroll
        for (int j = 0; j < 8; j++) {
            attn_s[(ty*4+i)*132 + tx*8 + j] = accA[i][j] + ba2[c0 + tx*8 + j];
            pos_s [(ty*4+i)*132 + tx*8 + j] = accP[i][j] + bp2[c0 + tx*8 + j];
        }
    __syncthreads();

#pragma unroll
    for (int e = tid; e < 512; e += 256) {
        int q = e >> 7;            // 0..3
        int c = e & 127;
        int mrow = q*16;
        float mx = -1e30f;
#pragma unroll
        for (int k = 0; k < KNN; k++)
            mx = fmaxf(mx, attn_s[(mrow+k)*132 + c]);
        float w[KNN]; float s = 0.f;
#pragma unroll
        for (int k = 0; k < KNN; k++) {
            w[k] = __expf(attn_s[(mrow+k)*132 + c] - mx);
            s += w[k];
        }
        float inv = 1.0f / s;
        int qg = (m0 >> 4) + q;
        int b = qg >> 11;
        float x = 0.f;
#pragma unroll
        for (int k = 0; k < KNN; k++) {
            int j = sj[mrow + k];
            float vv = g_v[(((size_t)b<<11) + j)*D + c0 + c] + pos_s[(mrow+k)*132 + c];
            x += vv * w[k];
        }
        g_x[(size_t)qg*D + c0 + c] = x * inv;
    }
}

// =================================================================================
extern "C" void kernel_launch(void* const* d_in, const int* in_sizes, int n_in,
                              void* d_out, int out_size)
{
    const float* dec_x   = (const float*)d_in[0];
    const float* dec_pc  = (const float*)d_in[1];
    const float* enc_x   = (const float*)d_in[2];
    const float* enc_pc  = (const float*)d_in[3];
    const float* W_pre1  = (const float*)d_in[4];
    const float* b_pre1  = (const float*)d_in[5];
    const float* W_pre2  = (const float*)d_in[6];
    const float* b_pre2  = (const float*)d_in[7];
    const float* Wq      = (const float*)d_in[8];
    const float* bq      = (const float*)d_in[9];
    const float* Wk      = (const float*)d_in[10];
    const float* bk      = (const float*)d_in[11];
    const float* Wv      = (const float*)d_in[12];
    const float* bv      = (const float*)d_in[13];
    const float* Wp1     = (const float*)d_in[14];
    const float* bp1     = (const float*)d_in[15];
    const float* gp      = (const float*)d_in[16];
    const float* betap   = (const float*)d_in[17];
    const float* Wp2     = (const float*)d_in[18];
    const float* bp2     = (const float*)d_in[19];
    const float* Wa1     = (const float*)d_in[20];
    const float* ba1     = (const float*)d_in[21];
    const float* ga      = (const float*)d_in[22];
    const float* betaa   = (const float*)d_in[23];
    const float* Wa2     = (const float*)d_in[24];
    const float* ba2     = (const float*)d_in[25];
    const float* W_post1 = (const float*)d_in[26];
    const float* b_post1 = (const float*)d_in[27];
    const float* W_post2 = (const float*)d_in[28];
    const float* b_post2 = (const float*)d_in[29];
    float* out = (float*)d_out;

    float *p_dx, *p_sx, *p_qa, *p_ka, *p_v, *p_hpos, *p_hattn, *p_x;
    float *p_WkWa1, *p_WqWa1, *p_stats;
    cudaGetSymbolAddress((void**)&p_dx,    g_dx);
    cudaGetSymbolAddress((void**)&p_sx,    g_sx);
    cudaGetSymbolAddress((void**)&p_qa,    g_qa);
    cudaGetSymbolAddress((void**)&p_ka,    g_ka);
    cudaGetSymbolAddress((void**)&p_v,     g_v);
    cudaGetSymbolAddress((void**)&p_hpos,  g_hpos);
    cudaGetSymbolAddress((void**)&p_hattn, g_hattn);
    cudaGetSymbolAddress((void**)&p_x,     g_x);
    cudaGetSymbolAddress((void**)&p_WkWa1, g_WkWa1);
    cudaGetSymbolAddress((void**)&p_WqWa1, g_WqWa1);
    cudaGetSymbolAddress((void**)&p_stats, g_stats);

    const int M8 = B*N1;                         // 8192
    const size_t FPS_SMEM  = 3*NC*sizeof(float);                 // 49152
    const size_t TF32_SMEM = (128*APITCH + 32*BPITCH)*sizeof(float); // 35840

    // 1) phase-1 mega-kernel: FPS || pre-projections || weight precomputes
    cudaFuncSetAttribute(phase1_kernel, cudaFuncAttributeMaxDynamicSharedMemorySize, (int)FPS_SMEM);
    phase1_kernel<<<271, 512, FPS_SMEM>>>(dec_pc, enc_pc, dec_x, enc_x,
                                          W_pre1, b_pre1, W_pre2, b_pre2,
                                          Wk, Wq, Wa1, Wp2, bk, bq, bp2, ba1);

    // 2) gather sampled features + coords
    gather_kernel<<<M8/4, 256>>>(dec_pc, enc_pc);

    // 3) KNN
    knn_kernel<<<dim3(N1/256, B), 256>>>(dec_pc);

    // 4) qa/ka (one fused launch) + v (tf32)
    gemm_n64_kernel<<<dim3(2, M8/128), 256>>>(p_dx, p_sx, p_WqWa1, p_WkWa1, p_qa, p_ka);
    gemm_tf32_kernel<<<dim3(2, M8/128), 512, TF32_SMEM>>>(p_sx, Wv, bv, nullptr, p_v, D, D);

    // 5) pos branch hidden + BN stats
    hpos_kernel<<<MROW/4, 256>>>(dec_pc, Wp1, bp1);
    colstats_kernel<<<256, 256>>>(p_hpos, MROW, p_stats + 0, p_stats + 64);
    finalize_bn_kernel<<<1, 64>>>(p_stats + 0, p_stats + 64, gp, betap,
                                  1.0f/(float)MROW, p_stats + 256, p_stats + 320);

    // 6) hattn compose + BN stats
    hattn_kernel<<<MROW/64, 256>>>();
    colstats_kernel<<<256, 256>>>(p_hattn, MROW, p_stats + 128, p_stats + 192);
    finalize_bn_kernel<<<1, 64>>>(p_stats + 128, p_stats + 192, ga, betaa,
                                  1.0f/(float)MROW, p_stats + 384, p_stats + 448);

    // 7) fused attn/pos GEMMs + softmax + aggregation
    cudaFuncSetAttribute(attnout_kernel, cudaFuncAttributeMaxDynamicSharedMemorySize, 124*1024);
    size_t smbytes = (size_t)(64*65*2 + 64*132*2 + 2*16*128)*sizeof(float) + 64*sizeof(int);
    attnout_kernel<<<dim3(2, MROW/64), 256, smbytes>>>(Wa2, ba2, Wp2, bp2);

    // 8) outputs (tf32)
    float* out1 = out;                                   // [B,N1,256]
    float* opc1 = out + (size_t)M8*D;                    // [B,N1,3]
    float* out2 = opc1 + (size_t)M8*3;                   // [B,N1,256]
    float* opc2 = out2 + (size_t)M8*D;                   // [B,N2,3]
    gemm_tf32_kernel<<<dim3(2, M8/128), 512, TF32_SMEM>>>(p_x, W_post1, b_post1, dec_x, out1, D, D);
    gemm_tf32_kernel<<<dim3(2, M8/128), 512, TF32_SMEM>>>(p_x, W_post2, b_post2, nullptr, out2, D, D);
    cudaMemcpyAsync(opc1, dec_pc, (size_t)M8*3*sizeof(float), cudaMemcpyDeviceToDevice);
    cudaMemcpyAsync(opc2, enc_pc, (size_t)B*N2*3*sizeof(float), cudaMemcpyDeviceToDevice);
}

// round 7
// speedup vs baseline: 1.6600x; 1.1921x over previous
#include <cuda_runtime.h>
#include <cuda_bf16.h>
#include <math.h>
#include <stdint.h>

// Problem constants
#define B    4
#define N1   2048
#define N2   2048
#define NC   4096           // N1+N2
#define D    256
#define HP   64
#define HA   64
#define KNN  16
#define MROW (B*N1*KNN)     // 131072

// ---------------- scratch (device globals; no allocation allowed) -------------
__device__ float g_dx  [B*N1*D];
__device__ float g_ex  [B*N2*D];
__device__ float g_sx  [B*N1*D];
__device__ float g_spc [B*N1*3];
__device__ int   g_fidx[B*N1];
__device__ float g_qa  [B*N1*HA];
__device__ float g_ka  [B*N1*HA];
__device__ float g_v   [B*N1*D];
__device__ int   g_nidx[B*N1*KNN];
__device__ float g_hpos [MROW*HP];
__device__ float g_hattn[MROW*HA];
__device__ float g_x   [B*N1*D];
__device__ float g_WkWa1[D*HA];
__device__ float g_WqWa1[D*HA];
__device__ float g_Wp2a [HP*HA];
__device__ float g_cvec [HA];
// [0:64) psum [64:128) psq [128:192) asum [192:256) asq
// [256:320) pscale [320:384) pshift [384:448) ascale [448:512) ashift
__device__ float g_stats[512];

// ================= tf32 mma helpers ===========================================
__device__ __forceinline__ uint32_t f2tf(float x) {
    uint32_t r; asm("cvt.rna.tf32.f32 %0, %1;" : "=r"(r) : "f"(x)); return r;
}
__device__ __forceinline__ void mma8(float* d, const uint32_t* a, const uint32_t* b) {
    asm volatile("mma.sync.aligned.m16n8k8.row.col.f32.tf32.tf32.f32 "
        "{%0,%1,%2,%3}, {%4,%5,%6,%7}, {%8,%9}, {%0,%1,%2,%3};"
        : "+f"(d[0]), "+f"(d[1]), "+f"(d[2]), "+f"(d[3])
        : "r"(a[0]), "r"(a[1]), "r"(a[2]), "r"(a[3]), "r"(b[0]), "r"(b[1]));
}

// ------ tf32x2 GEMM body: 128x128 tile, 512 threads, hi/lo planes, 3-mma ------
#define APITCH 36
#define BPITCH 136
// dyn smem floats: AH[128*36] AL[128*36] BH[32*136] BL[32*136]  (71680 B)
#define TF32_SMEM_FLOATS (2*128*APITCH + 2*32*BPITCH)

__device__ __forceinline__ void gemm_tf32_body(
    const float* __restrict__ A, const float* __restrict__ W,
    const float* __restrict__ bias, const float* __restrict__ resid,
    float* __restrict__ C, int bx, int by, int N, int K)
{
    extern __shared__ float smext[];
    float* AHs = smext;
    float* ALs = AHs + 128*APITCH;
    float* BHs = ALs + 128*APITCH;
    float* BLs = BHs + 32*BPITCH;
    int tid = threadIdx.x;
    int row0 = by * 128, col0 = bx * 128;
    int warp = tid >> 5, lane = tid & 31;
    int mw = (warp & 3) * 32, nw = (warp >> 2) * 32;
    int g = lane >> 2, tg = lane & 3;
    float acc[8][4] = {};
    for (int k0 = 0; k0 < K; k0 += 32) {
#pragma unroll
        for (int i = 0; i < 2; i++) {
            int idx = tid + i*512;
            int r = idx >> 3, c4 = (idx & 7) * 4;
            float4 v = *(const float4*)&A[(size_t)(row0+r)*K + k0 + c4];
            float xs[4] = {v.x, v.y, v.z, v.w};
#pragma unroll
            for (int u = 0; u < 4; u++) {
                uint32_t hi = f2tf(xs[u]);
                AHs[r*APITCH + c4+u] = __uint_as_float(hi);
                ALs[r*APITCH + c4+u] = __uint_as_float(f2tf(xs[u] - __uint_as_float(hi)));
            }
        }
#pragma unroll
        for (int i = 0; i < 2; i++) {
            int idx = tid + i*512;
            int r = idx >> 5, c4 = (idx & 31) * 4;
            float4 v = *(const float4*)&W[(size_t)(k0+r)*N + col0 + c4];
            float xs[4] = {v.x, v.y, v.z, v.w};
#pragma unroll
            for (int u = 0; u < 4; u++) {
                uint32_t hi = f2tf(xs[u]);
                BHs[r*BPITCH + c4+u] = __uint_as_float(hi);
                BLs[r*BPITCH + c4+u] = __uint_as_float(f2tf(xs[u] - __uint_as_float(hi)));
            }
        }
        __syncthreads();
#pragma unroll
        for (int ks = 0; ks < 32; ks += 8) {
            uint32_t ah[2][4], al[2][4], bh[4][2], bl[4][2];
#pragma unroll
            for (int mi = 0; mi < 2; mi++) {
                int rb = mw + mi*16;
                ah[mi][0] = __float_as_uint(AHs[(rb+g  )*APITCH + ks+tg  ]);
                ah[mi][1] = __float_as_uint(AHs[(rb+g+8)*APITCH + ks+tg  ]);
                ah[mi][2] = __float_as_uint(AHs[(rb+g  )*APITCH + ks+tg+4]);
                ah[mi][3] = __float_as_uint(AHs[(rb+g+8)*APITCH + ks+tg+4]);
                al[mi][0] = __float_as_uint(ALs[(rb+g  )*APITCH + ks+tg  ]);
                al[mi][1] = __float_as_uint(ALs[(rb+g+8)*APITCH + ks+tg  ]);
                al[mi][2] = __float_as_uint(ALs[(rb+g  )*APITCH + ks+tg+4]);
                al[mi][3] = __float_as_uint(ALs[(rb+g+8)*APITCH + ks+tg+4]);
            }
#pragma unroll
            for (int ni = 0; ni < 4; ni++) {
                bh[ni][0] = __float_as_uint(BHs[(ks+tg  )*BPITCH + nw + ni*8 + g]);
                bh[ni][1] = __float_as_uint(BHs[(ks+tg+4)*BPITCH + nw + ni*8 + g]);
                bl[ni][0] = __float_as_uint(BLs[(ks+tg  )*BPITCH + nw + ni*8 + g]);
                bl[ni][1] = __float_as_uint(BLs[(ks+tg+4)*BPITCH + nw + ni*8 + g]);
            }
#pragma unroll
            for (int mi = 0; mi < 2; mi++)
#pragma unroll
                for (int ni = 0; ni < 4; ni++) {
                    mma8(acc[mi*4+ni], ah[mi], bh[ni]);
                    mma8(acc[mi*4+ni], ah[mi], bl[ni]);
                    mma8(acc[mi*4+ni], al[mi], bh[ni]);
                }
        }
        __syncthreads();
    }
#pragma unroll
    for (int mi = 0; mi < 2; mi++) {
#pragma unroll
        for (int ni = 0; ni < 4; ni++) {
            int c = col0 + nw + ni*8 + 2*tg;
            float b0 = bias ? bias[c]   : 0.f;
            float b1 = bias ? bias[c+1] : 0.f;
            size_t r1 = (size_t)(row0 + mw + mi*16 + g);
            size_t r2 = r1 + 8;
            float v00 = acc[mi*4+ni][0] + b0, v01 = acc[mi*4+ni][1] + b1;
            float v10 = acc[mi*4+ni][2] + b0, v11 = acc[mi*4+ni][3] + b1;
            if (resid) {
                v00 += resid[r1*N+c]; v01 += resid[r1*N+c+1];
                v10 += resid[r2*N+c]; v11 += resid[r2*N+c+1];
            }
            *(float2*)&C[r1*N + c] = make_float2(v00, v01);
            *(float2*)&C[r2*N + c] = make_float2(v10, v11);
        }
    }
}

// ---------------- combined post-GEMMs (z selects output head) ------------------
__global__ void __launch_bounds__(512)
gemm_post_kernel(const float* __restrict__ X,
                 const float* __restrict__ W1, const float* __restrict__ b1,
                 const float* __restrict__ resid1, float* __restrict__ out1,
                 const float* __restrict__ W2, const float* __restrict__ b2,
                 float* __restrict__ out2)
{
    if (blockIdx.z == 0)
        gemm_tf32_body(X, W1, b1, resid1, out1, blockIdx.x, blockIdx.y, D, D);
    else
        gemm_tf32_body(X, W2, b2, nullptr, out2, blockIdx.x, blockIdx.y, D, D);
}

// ---------------- FPS body: 512 threads, register-resident coords --------------
__device__ void fps_body(int b, const float* __restrict__ decpc,
                         const float* __restrict__ encpc)
{
    extern __shared__ float smext[];
    float* sx = smext;
    float* sy = smext + NC;
    float* sz = smext + 2*NC;
    __shared__ unsigned long long swk[2][16];

    int tid = threadIdx.x;
    int wid = tid >> 5, lid = tid & 31;

    for (int j = tid; j < N1; j += 512) {
        sx[j] = decpc[((size_t)b*N1 + j)*3 + 0];
        sy[j] = decpc[((size_t)b*N1 + j)*3 + 1];
        sz[j] = decpc[((size_t)b*N1 + j)*3 + 2];
        sx[N1+j] = encpc[((size_t)b*N2 + j)*3 + 0];
        sy[N1+j] = encpc[((size_t)b*N2 + j)*3 + 1];
        sz[N1+j] = encpc[((size_t)b*N2 + j)*3 + 2];
    }
    if (tid == 0) g_fidx[b*N1] = 0;
    int cur = 0;
    __syncthreads();

    // coords into registers (never change)
    float X[8], Y[8], Z[8], md[8];
#pragma unroll
    for (int t = 0; t < 8; t++) {
        int j = tid + t*512;
        X[t] = sx[j]; Y[t] = sy[j]; Z[t] = sz[j];
        md[t] = 1e10f;
    }

    for (int i = 1; i < N1; i++) {
        float lx = sx[cur], ly = sy[cur], lz = sz[cur];
        float bestv = -1.0f; int besti = 0x7fffffff;
#pragma unroll
        for (int t = 0; t < 8; t++) {
            float ddx = X[t]-lx, ddy = Y[t]-ly, ddz = Z[t]-lz;
            float d = ddx*ddx + ddy*ddy + ddz*ddz;
            float mm = fminf(md[t], d);
            md[t] = mm;
            if (mm > bestv) { bestv = mm; besti = tid + t*512; }
        }
        unsigned kb = __float_as_uint(bestv);
        kb = ((int)kb < 0) ? ~kb : (kb | 0x80000000u);
        unsigned mk;
        asm("redux.sync.max.u32 %0, %1, 0xffffffff;" : "=r"(mk) : "r"(kb));
        unsigned idxc = (kb == mk) ? (unsigned)besti : 0xffffffffu;
        unsigned mi;
        asm("redux.sync.min.u32 %0, %1, 0xffffffff;" : "=r"(mi) : "r"(idxc));
        int pb = i & 1;
        if (lid == 0)
            swk[pb][wid] = (((unsigned long long)mk) << 32) | (unsigned long long)(0xffffffffu - mi);
        __syncthreads();
        unsigned long long best = swk[pb][0];
#pragma unroll
        for (int w = 1; w < 16; w++) {
            unsigned long long o = swk[pb][w];
            best = (o > best) ? o : best;
        }
        cur = (int)(0xffffffffu - (unsigned)best);
        if (tid == 0) g_fidx[b*N1 + i] = cur;
    }
}

// ---------------- small 64-col GEMM body (weight precomputes), 512 thr --------
#define TBM 64
#define TBK 16
__device__ void gemm64_body(const float* __restrict__ A, const float* __restrict__ W,
                            float* __restrict__ C, int row0, int N, int K)
{
    __shared__ float As64[TBK][TBM];
    __shared__ float Bs64[TBK][64];
    int tid = threadIdx.x;
    for (int k0 = 0; k0 < K; k0 += TBK) {
#pragma unroll
        for (int u = 0; u < 2; u++) {
            int e = tid + u*512;
            int r = e >> 4, c = e & 15;
            As64[c][r] = A[(size_t)(row0 + r)*K + k0 + c];
            int r2 = e >> 6, c2 = e & 63;
            Bs64[r2][c2] = W[(size_t)(k0 + r2)*N + c2];
        }
        __syncthreads();
        if (tid < 256) {
            int tx = tid & 15, ty = tid >> 4;
            float acc[4][4] = {};
#pragma unroll
            for (int kk = 0; kk < TBK; kk++) {
                float a[4], bb[4];
#pragma unroll
                for (int i = 0; i < 4; i++) a[i] = As64[kk][ty*4+i];
#pragma unroll
                for (int j = 0; j < 4; j++) bb[j] = Bs64[kk][tx*4+j];
#pragma unroll
                for (int i = 0; i < 4; i++)
#pragma unroll
                    for (int j = 0; j < 4; j++)
                        acc[i][j] += a[i]*bb[j];
            }
#pragma unroll
            for (int i = 0; i < 4; i++)
#pragma unroll
                for (int j = 0; j < 4; j++) {
                    size_t off = (size_t)(row0 + ty*4 + i)*N + tx*4 + j;
                    if (k0 == 0) C[off] = acc[i][j];
                    else         C[off] += acc[i][j];
                }
        }
        __syncthreads();
    }
}

// ---------------- cvec body: (bk - bq + bp2) @ Wa1 + ba1, 512 thr --------------
__device__ void cvec_body(const float* __restrict__ bk, const float* __restrict__ bq,
                          const float* __restrict__ bp2, const float* __restrict__ Wa1,
                          const float* __restrict__ ba1)
{
    __shared__ float shc[512];
    int c = threadIdx.x & 63;
    int part = threadIdx.x >> 6;     // 0..7
    float s = 0.f;
    for (int i = part*32; i < part*32 + 32; i++)
        s += (bk[i] - bq[i] + bp2[i]) * Wa1[(size_t)i*HA + c];
    shc[threadIdx.x] = s;
    __syncthreads();
    if (part == 0) {
        float t = ba1[c];
#pragma unroll
        for (int p = 0; p < 8; p++) t += shc[p*64 + c];
        g_cvec[c] = t;
    }
}

// ---------------- phase-1 mega-kernel -----------------------------------------
// blocks: [0,4)=FPS  [4,132)=pre1 gemm  [132,260)=pre2 gemm
//         [260,264)=WkWa1 [264,268)=WqWa1 [268]=Wp2a [269]=cvec [270]=zero_stats
__global__ void __launch_bounds__(512)
phase1_kernel(const float* __restrict__ dec_pc, const float* __restrict__ enc_pc,
              const float* __restrict__ dec_x,  const float* __restrict__ enc_x,
              const float* __restrict__ W_pre1, const float* __restrict__ b_pre1,
              const float* __restrict__ W_pre2, const float* __restrict__ b_pre2,
              const float* __restrict__ Wk, const float* __restrict__ Wq,
              const float* __restrict__ Wa1, const float* __restrict__ Wp2,
              const float* __restrict__ bk, const float* __restrict__ bq,
              const float* __restrict__ bp2, const float* __restrict__ ba1)
{
    int bid = blockIdx.x;
    if (bid < 4) {
        fps_body(bid, dec_pc, enc_pc);
    } else if (bid < 132) {
        int t = bid - 4;
        gemm_tf32_body(dec_x, W_pre1, b_pre1, nullptr, g_dx, t & 1, t >> 1, D, D);
    } else if (bid < 260) {
        int t = bid - 132;
        gemm_tf32_body(enc_x, W_pre2, b_pre2, nullptr, g_ex, t & 1, t >> 1, D, D);
    } else if (bid < 264) {
        gemm64_body(Wk, Wa1, g_WkWa1, (bid-260)*64, HA, D);
    } else if (bid < 268) {
        gemm64_body(Wq, Wa1, g_WqWa1, (bid-264)*64, HA, D);
    } else if (bid == 268) {
        gemm64_body(Wp2, Wa1, g_Wp2a, 0, HA, D);
    } else if (bid == 269) {
        cvec_body(bk, bq, bp2, Wa1, ba1);
    } else {
        g_stats[threadIdx.x] = 0.0f;
    }
}

// ---------------- gather sampled features + coords ----------------------------
__global__ void gather_kernel(const float* __restrict__ decpc,
                              const float* __restrict__ encpc)
{
    int row = blockIdx.x*4 + (threadIdx.x >> 6);
    int c4  = (threadIdx.x & 63) * 4;
    int b = row >> 11;
    int j = g_fidx[row];
    const float* src = (j < N1) ? &g_dx[((size_t)b*N1 + j)*D]
                                : &g_ex[((size_t)b*N2 + (j - N1))*D];
    *(float4*)&g_sx[(size_t)row*D + c4] = *(const float4*)&src[c4];
    if ((threadIdx.x & 63) < 3) {
        int cc = threadIdx.x & 63;
        const float* ps = (j < N1) ? &decpc[((size_t)b*N1 + j)*3]
                                   : &encpc[((size_t)b*N2 + (j - N1))*3];
        g_spc[(size_t)row*3 + cc] = ps[cc];
    }
}

// ---------------- N=64 GEMM body for 512 threads (qa/ka) -----------------------
__device__ void n64_body_512(const float* __restrict__ A, const float* __restrict__ W,
                             float* __restrict__ C, int row0)
{
    __shared__ float Asq[16][132];
    __shared__ float Bsq[16][64];
    int tid = threadIdx.x;
    int tx = tid & 15, ty = tid >> 4;          // ty 0..31
    float acc[4][4] = {};
    for (int k0 = 0; k0 < D; k0 += 16) {
        {
            int r = tid >> 2, kq = (tid & 3) * 4;
            float4 va = *(const float4*)&A[(size_t)(row0 + r)*D + k0 + kq];
            Asq[kq+0][r] = va.x; Asq[kq+1][r] = va.y;
            Asq[kq+2][r] = va.z; Asq[kq+3][r] = va.w;
        }
        if (tid < 256) {
            int r = tid >> 4, cq = (tid & 15) * 4;
            *(float4*)&Bsq[r][cq] = *(const float4*)&W[(size_t)(k0 + r)*HA + cq];
        }
        __syncthreads();
#pragma unroll
        for (int kk = 0; kk < 16; kk++) {
            float a[4], bb[4];
#pragma unroll
            for (int i = 0; i < 4; i++) a[i] = Asq[kk][ty*4+i];
#pragma unroll
            for (int j = 0; j < 4; j++) bb[j] = Bsq[kk][tx*4+j];
#pragma unroll
            for (int i = 0; i < 4; i++)
#pragma unroll
                for (int j = 0; j < 4; j++)
                    acc[i][j] += a[i]*bb[j];
        }
        __syncthreads();
    }
#pragma unroll
    for (int i = 0; i < 4; i++)
#pragma unroll
        for (int j = 0; j < 4; j++)
            C[(size_t)(row0 + ty*4 + i)*HA + tx*4 + j] = acc[i][j];
}

// ---------------- phase-2 mega-kernel: KNN + qa/ka + v -------------------------
// blocks: [0,32)=knn (2 threads/query)  [32,160)=qa/ka  [160,288)=v tf32
__global__ void __launch_bounds__(512)
phase2_kernel(const float* __restrict__ decpc,
              const float* __restrict__ Wv, const float* __restrict__ bv)
{
    int bid = blockIdx.x;
    if (bid < 32) {
        extern __shared__ float s2[];
        float* px = s2; float* py = px + 2048; float* pz = py + 2048; float* s2s = pz + 2048;
        unsigned long long* buf = (unsigned long long*)(s2 + 8192);
        int tid = threadIdx.x;
        int b = bid >> 3, qb = bid & 7;
        for (int m = tid; m < 2048; m += 512) {
            float x = g_spc[((size_t)b*N1 + m)*3 + 0];
            float y = g_spc[((size_t)b*N1 + m)*3 + 1];
            float z = g_spc[((size_t)b*N1 + m)*3 + 2];
            px[m] = x; py[m] = y; pz[m] = z;
            s2s[m] = x*x + y*y + z*z;
        }
        __syncthreads();
        int qi = tid & 255, h = tid >> 8;
        int q = qb*256 + qi;
        float qx = decpc[((size_t)b*N1 + q)*3 + 0];
        float qy = decpc[((size_t)b*N1 + q)*3 + 1];
        float qz = decpc[((size_t)b*N1 + q)*3 + 2];
        float s1 = qx*qx + qy*qy + qz*qz;
        float bd[KNN]; int bi[KNN];
#pragma unroll
        for (int t = 0; t < KNN; t++) { bd[t] = 1e30f; bi[t] = 0; }
        int mbase = h * 1024;
        for (int mm = 0; mm < 1024; mm++) {
            int m = mbase + mm;
            float d = s1 + s2s[m] - 2.0f*(qx*px[m] + qy*py[m] + qz*pz[m]);
            if (d < bd[KNN-1]) {
                bd[KNN-1] = d; bi[KNN-1] = m;
#pragma unroll
                for (int t = KNN-1; t > 0; t--) {
                    if (bd[t] < bd[t-1]) {
                        float td = bd[t]; bd[t] = bd[t-1]; bd[t-1] = td;
                        int   ti = bi[t]; bi[t] = bi[t-1]; bi[t-1] = ti;
                    }
                }
            }
        }
#pragma unroll
        for (int t = 0; t < KNN; t++) {
            unsigned u = __float_as_uint(bd[t]);
            u = ((int)u < 0) ? ~u : (u | 0x80000000u);
            buf[(size_t)tid*KNN + t] = (((unsigned long long)u) << 32) | (unsigned)bi[t];
        }
        __syncthreads();
        if (h == 0) {
            const unsigned long long* A_ = &buf[(size_t)qi*KNN];
            const unsigned long long* B_ = &buf[(size_t)(qi+256)*KNN];
            int* outp = &g_nidx[((size_t)b*N1 + q)*KNN];
            int ia = 0, ib = 0;
#pragma unroll
            for (int o = 0; o < KNN; o++) {
                unsigned long long av = A_[ia], bv_ = B_[ib];
                if ((av >> 32) <= (bv_ >> 32)) { outp[o] = (int)(unsigned)av; ia++; }
                else                           { outp[o] = (int)(unsigned)bv_; ib++; }
            }
        }
    } else if (bid < 160) {
        int t = bid - 32;
        int sel = t >> 6, tile = t & 63;
        n64_body_512(sel ? g_sx : g_dx, sel ? g_WkWa1 : g_WqWa1,
                     sel ? g_ka : g_qa, tile*128);
    } else {
        int t = bid - 160;
        gemm_tf32_body(g_sx, Wv, bv, nullptr, g_v, t & 1, t >> 1, D, D);
    }
}

// ---------------- hpos: pos_in @ Wp1 + bp1 ------------------------------------
__global__ void hpos_kernel(const float* __restrict__ decpc,
                            const float* __restrict__ Wp1,
                            const float* __restrict__ bp1)
{
    int m = blockIdx.x*4 + (threadIdx.x >> 6);
    int c = threadIdx.x & 63;
    int b = m >> 15;
    int n = (m >> 4) & 2047;
    int j = g_nidx[m];
    const float* pp = &g_spc[((size_t)b*N1 + j)*3];
    const float* qq = &decpc[((size_t)b*N1 + n)*3];
    float p0 = pp[0]-qq[0], p1 = pp[1]-qq[1], p2 = pp[2]-qq[2];
    float h = p0*Wp1[c] + p1*Wp1[64+c] + p2*Wp1[128+c] + bp1[c];
    g_hpos[(size_t)m*HP + c] = h;
}

// ---------------- column stats over [M,64] matrix ------------------------------
__global__ void colstats_kernel(const float* __restrict__ X, int M,
                                float* __restrict__ sum, float* __restrict__ sumsq)
{
    int c  = threadIdx.x & 63;
    int rg = threadIdx.x >> 6;
    float s = 0.f, s2 = 0.f;
    for (int r = blockIdx.x*4 + rg; r < M; r += gridDim.x*4) {
        float v = X[(size_t)r*64 + c];
        s += v; s2 += v*v;
    }
    __shared__ float sh[256], sh2[256];
    sh[threadIdx.x] = s; sh2[threadIdx.x] = s2;
    __syncthreads();
    if (rg == 0) {
        s  = sh[c]  + sh[64+c]  + sh[128+c]  + sh[192+c];
        s2 = sh2[c] + sh2[64+c] + sh2[128+c] + sh2[192+c];
        atomicAdd(&sum[c], s);
        atomicAdd(&sumsq[c], s2);
    }
}

__global__ void finalize_bn_kernel(const float* __restrict__ sum,
                                   const float* __restrict__ sumsq,
                                   const float* __restrict__ g,
                                   const float* __restrict__ beta,
                                   float invM,
                                   float* __restrict__ scale,
                                   float* __restrict__ shift)
{
    int c = threadIdx.x;
    float mean = sum[c]*invM;
    float var  = sumsq[c]*invM - mean*mean;
    float sc = g[c]*rsqrtf(var + 1e-5f);
    scale[c] = sc;
    shift[c] = beta[c] - mean*sc;
}

// ---- hattn = relu(bn_pos(hp)) @ Wp2a + ka[gather] - qa + cvec  ([M,64]) ------
__global__ void __launch_bounds__(256)
hattn_kernel()
{
    __shared__ float Aw[64][65];
    __shared__ float Bw[64*64];
    int tid = threadIdx.x;
    int m0 = blockIdx.x * 64;
#pragma unroll
    for (int i = 0; i < 16; i++) {
        int idx = tid + i*256;
        int r = idx >> 6, k = idx & 63;
        float h = g_hpos[(size_t)(m0+r)*64 + k];
        Aw[r][k] = fmaxf(h*g_stats[256+k] + g_stats[320+k], 0.0f);
        Bw[idx] = g_Wp2a[idx];
    }
    __syncthreads();
    int tx = tid & 15, ty = tid >> 4;
    float acc[4][4] = {};
#pragma unroll 4
    for (int kk = 0; kk < 64; kk++) {
        float a[4], bb[4];
#pragma unroll
        for (int i = 0; i < 4; i++) a[i] = Aw[ty*4+i][kk];
#pragma unroll
        for (int j = 0; j < 4; j++) bb[j] = Bw[kk*64 + tx*4 + j];
#pragma unroll
        for (int i = 0; i < 4; i++)
#pragma unroll
            for (int j = 0; j < 4; j++)
                acc[i][j] += a[i]*bb[j];
    }
#pragma unroll
    for (int i = 0; i < 4; i++) {
        int m = m0 + ty*4 + i;
        int b = m >> 15;
        int n = (m >> 4) & 2047;
        int jj = g_nidx[m];
        const float* kar = &g_ka[(((size_t)b<<11) + jj)*HA];
        const float* qar = &g_qa[(((size_t)b<<11) + n )*HA];
#pragma unroll
        for (int j = 0; j < 4; j++) {
            int c = tx*4 + j;
            g_hattn[(size_t)m*HA + c] = acc[i][j] + kar[c] - qar[c] + g_cvec[c];
        }
    }
}

// ---- fused: attn/pos GEMMs via tf32x2 mma + softmax(K) + agg -> g_x ----------
// block: 64 rows x 128 cols, 256 threads (8 warps: 4 M-tiles x 2 N-halves)
__global__ void __launch_bounds__(256)
attnout_kernel(const float* __restrict__ Wa2,
               const float* __restrict__ ba2,
               const float* __restrict__ Wp2,
               const float* __restrict__ bp2)
{
    extern __shared__ float sm[];
    float* Ahr    = sm;                 // [64][68] raw bn-relu(hattn)
    float* Apr    = Ahr + 64*68;        // [64][68]
    float* attn_s = Apr + 64*68;        // [64][132]
    float* pos_s  = attn_s + 64*132;    // [64][132]
    float* Bh     = pos_s + 64*132;     // [16][136]
    float* Bl     = Bh + 16*136;        // [16][136]
    int*   sj     = (int*)(Bl + 16*136);// [64]

    int tid = threadIdx.x;
    int m0 = blockIdx.y * 64;
    int c0 = blockIdx.x * 128;
    int warp = tid >> 5, lane = tid & 31;
    int mw = (warp & 3) * 16, nw = (warp >> 2) * 64;
    int g = lane >> 2, tg = lane & 3;

#pragma unroll
    for (int i = 0; i < 16; i++) {
        int idx = tid + i*256;
        int r = idx >> 6, k = idx & 63;
        float ha = g_hattn[(size_t)(m0+r)*64 + k];
        Ahr[r*68 + k] = fmaxf(ha*g_stats[384+k] + g_stats[448+k], 0.0f);
        float hp = g_hpos[(size_t)(m0+r)*64 + k];
        Apr[r*68 + k] = fmaxf(hp*g_stats[256+k] + g_stats[320+k], 0.0f);
    }
    if (tid < 64) sj[tid] = g_nidx[m0 + tid];

#pragma unroll
    for (int pass = 0; pass < 2; pass++) {
        const float* Wsrc = pass ? Wp2 : Wa2;
        const float* bsrc = pass ? bp2 : ba2;
        const float* Asm  = pass ? Apr : Ahr;
        float* Out = pass ? pos_s : attn_s;
        float acc[8][4] = {};
        for (int k0 = 0; k0 < 64; k0 += 16) {
            __syncthreads();
#pragma unroll
            for (int i = 0; i < 8; i++) {
                int idx = tid + i*256;
                int r = idx >> 7, c = idx & 127;
                float x = Wsrc[(size_t)(k0+r)*D + c0 + c];
                uint32_t hi = f2tf(x);
                Bh[r*136 + c] = __uint_as_float(hi);
                Bl[r*136 + c] = __uint_as_float(f2tf(x - __uint_as_float(hi)));
            }
            __syncthreads();
#pragma unroll
            for (int ks = 0; ks < 16; ks += 8) {
                uint32_t ah[4], al[4];
                {
                    float x0 = Asm[(mw+g  )*68 + k0+ks+tg  ];
                    float x1 = Asm[(mw+g+8)*68 + k0+ks+tg  ];
                    float x2 = Asm[(mw+g  )*68 + k0+ks+tg+4];
                    float x3 = Asm[(mw+g+8)*68 + k0+ks+tg+4];
                    ah[0] = f2tf(x0); al[0] = f2tf(x0 - __uint_as_float(ah[0]));
                    ah[1] = f2tf(x1); al[1] = f2tf(x1 - __uint_as_float(ah[1]));
                    ah[2] = f2tf(x2); al[2] = f2tf(x2 - __uint_as_float(ah[2]));
                    ah[3] = f2tf(x3); al[3] = f2tf(x3 - __uint_as_float(ah[3]));
                }
#pragma unroll
                for (int ni = 0; ni < 8; ni++) {
                    uint32_t bhf[2], blf[2];
                    bhf[0] = __float_as_uint(Bh[(ks+tg  )*136 + nw + ni*8 + g]);
                    bhf[1] = __float_as_uint(Bh[(ks+tg+4)*136 + nw + ni*8 + g]);
                    blf[0] = __float_as_uint(Bl[(ks+tg  )*136 + nw + ni*8 + g]);
                    blf[1] = __float_as_uint(Bl[(ks+tg+4)*136 + nw + ni*8 + g]);
                    mma8(acc[ni], ah, bhf);
                    mma8(acc[ni], ah, blf);
                    mma8(acc[ni], al, bhf);
                }
            }
        }
#pragma unroll
        for (int ni = 0; ni < 8; ni++) {
            int c = nw + ni*8 + 2*tg;
            float b0 = bsrc[c0 + c], b1 = bsrc[c0 + c + 1];
            Out[(mw+g  )*132 + c]     = acc[ni][0] + b0;
            Out[(mw+g  )*132 + c + 1] = acc[ni][1] + b1;
            Out[(mw+g+8)*132 + c]     = acc[ni][2] + b0;
            Out[(mw+g+8)*132 + c + 1] = acc[ni][3] + b1;
        }
    }
    __syncthreads();

    // ---- softmax over 16 neighbors + aggregation
#pragma unroll
    for (int e = tid; e < 512; e += 256) {
        int q = e >> 7;            // 0..3
        int c = e & 127;
        int mrow = q*16;
        float mx = -1e30f;
#pragma unroll
        for (int k = 0; k < KNN; k++)
            mx = fmaxf(mx, attn_s[(mrow+k)*132 + c]);
        float w[KNN]; float s = 0.f;
#pragma unroll
        for (int k = 0; k < KNN; k++) {
            w[k] = __expf(attn_s[(mrow+k)*132 + c] - mx);
            s += w[k];
        }
        float inv = 1.0f / s;
        int qg = (m0 >> 4) + q;
        int b = qg >> 11;
        float x = 0.f;
#pragma unroll
        for (int k = 0; k < KNN; k++) {
            int j = sj[mrow + k];
            float vv = g_v[(((size_t)b<<11) + j)*D + c0 + c] + pos_s[(mrow+k)*132 + c];
            x += vv * w[k];
        }
        g_x[(size_t)qg*D + c0 + c] = x * inv;
    }
}

// =================================================================================
extern "C" void kernel_launch(void* const* d_in, const int* in_sizes, int n_in,
                              void* d_out, int out_size)
{
    const float* dec_x   = (const float*)d_in[0];
    const float* dec_pc  = (const float*)d_in[1];
    const float* enc_x   = (const float*)d_in[2];
    const float* enc_pc  = (const float*)d_in[3];
    const float* W_pre1  = (const float*)d_in[4];
    const float* b_pre1  = (const float*)d_in[5];
    const float* W_pre2  = (const float*)d_in[6];
    const float* b_pre2  = (const float*)d_in[7];
    const float* Wq      = (const float*)d_in[8];
    const float* bq      = (const float*)d_in[9];
    const float* Wk      = (const float*)d_in[10];
    const float* bk      = (const float*)d_in[11];
    const float* Wv      = (const float*)d_in[12];
    const float* bv      = (const float*)d_in[13];
    const float* Wp1     = (const float*)d_in[14];
    const float* bp1     = (const float*)d_in[15];
    const float* gp      = (const float*)d_in[16];
    const float* betap   = (const float*)d_in[17];
    const float* Wp2     = (const float*)d_in[18];
    const float* bp2     = (const float*)d_in[19];
    const float* Wa1     = (const float*)d_in[20];
    const float* ba1     = (const float*)d_in[21];
    const float* ga      = (const float*)d_in[22];
    const float* betaa   = (const float*)d_in[23];
    const float* Wa2     = (const float*)d_in[24];
    const float* ba2     = (const float*)d_in[25];
    const float* W_post1 = (const float*)d_in[26];
    const float* b_post1 = (const float*)d_in[27];
    const float* W_post2 = (const float*)d_in[28];
    const float* b_post2 = (const float*)d_in[29];
    float* out = (float*)d_out;

    float *p_hpos, *p_hattn, *p_x, *p_stats;
    cudaGetSymbolAddress((void**)&p_hpos,  g_hpos);
    cudaGetSymbolAddress((void**)&p_hattn, g_hattn);
    cudaGetSymbolAddress((void**)&p_x,     g_x);
    cudaGetSymbolAddress((void**)&p_stats, g_stats);

    const int M8 = B*N1;                         // 8192
    const int PH1_SMEM  = TF32_SMEM_FLOATS*4;                 // 71680 (>= FPS 49152)
    const int PH2_SMEM  = 8192*4 + 512*KNN*8;                 // 98304
    const int ATTN_SMEM = (64*68*2 + 64*132*2 + 16*136*2)*4 + 64*4; // 120064
    const int POST_SMEM = TF32_SMEM_FLOATS*4;

    // 1) phase-1: FPS || pre-projections || weight precomputes || cvec || zero
    cudaFuncSetAttribute(phase1_kernel, cudaFuncAttributeMaxDynamicSharedMemorySize, PH1_SMEM);
    phase1_kernel<<<271, 512, PH1_SMEM>>>(dec_pc, enc_pc, dec_x, enc_x,
                                          W_pre1, b_pre1, W_pre2, b_pre2,
                                          Wk, Wq, Wa1, Wp2, bk, bq, bp2, ba1);

    // 2) gather sampled features + coords
    gather_kernel<<<M8/4, 256>>>(dec_pc, enc_pc);

    // 3) phase-2: KNN || qa/ka || v
    cudaFuncSetAttribute(phase2_kernel, cudaFuncAttributeMaxDynamicSharedMemorySize, PH2_SMEM);
    phase2_kernel<<<288, 512, PH2_SMEM>>>(dec_pc, Wv, bv);

    // 4) pos branch hidden + BN stats
    hpos_kernel<<<MROW/4, 256>>>(dec_pc, Wp1, bp1);
    colstats_kernel<<<256, 256>>>(p_hpos, MROW, p_stats + 0, p_stats + 64);
    finalize_bn_kernel<<<1, 64>>>(p_stats + 0, p_stats + 64, gp, betap,
                                  1.0f/(float)MROW, p_stats + 256, p_stats + 320);

    // 5) hattn compose + BN stats
    hattn_kernel<<<MROW/64, 256>>>();
    colstats_kernel<<<256, 256>>>(p_hattn, MROW, p_stats + 128, p_stats + 192);
    finalize_bn_kernel<<<1, 64>>>(p_stats + 128, p_stats + 192, ga, betaa,
                                  1.0f/(float)MROW, p_stats + 384, p_stats + 448);

    // 6) fused attn/pos mma GEMMs + softmax + aggregation
    cudaFuncSetAttribute(attnout_kernel, cudaFuncAttributeMaxDynamicSharedMemorySize, ATTN_SMEM);
    attnout_kernel<<<dim3(2, MROW/64), 256, ATTN_SMEM>>>(Wa2, ba2, Wp2, bp2);

    // 7) outputs (both post GEMMs in one launch)
    float* out1 = out;                                   // [B,N1,256]
    float* opc1 = out + (size_t)M8*D;                    // [B,N1,3]
    float* out2 = opc1 + (size_t)M8*3;                   // [B,N1,256]
    float* opc2 = out2 + (size_t)M8*D;                   // [B,N2,3]
    cudaFuncSetAttribute(gemm_post_kernel, cudaFuncAttributeMaxDynamicSharedMemorySize, POST_SMEM);
    gemm_post_kernel<<<dim3(2, M8/128, 2), 512, POST_SMEM>>>(p_x, W_post1, b_post1, dec_x, out1,
                                                             W_post2, b_post2, out2);
    cudaMemcpyAsync(opc1, dec_pc, (size_t)M8*3*sizeof(float), cudaMemcpyDeviceToDevice);
    cudaMemcpyAsync(opc2, enc_pc, (size_t)B*N2*3*sizeof(float), cudaMemcpyDeviceToDevice);
}

// round 8
// speedup vs baseline: 1.7024x; 1.0256x over previous
#include <cuda_runtime.h>
#include <cuda_bf16.h>
#include <math.h>
#include <stdint.h>

// Problem constants
#define B    4
#define N1   2048
#define N2   2048
#define NC   4096           // N1+N2
#define D    256
#define HP   64
#define HA   64
#define KNN  16
#define MROW (B*N1*KNN)     // 131072
#define INV_MROW (1.0f/131072.0f)

// ---------------- scratch (device globals; no allocation allowed) -------------
__device__ float g_dx  [B*N1*D];
__device__ float g_ex  [B*N2*D];
__device__ float g_sx  [B*N1*D];
__device__ float g_spc [B*N1*3];
__device__ int   g_fidx[B*N1];
__device__ float g_qa  [B*N1*HA];
__device__ float g_ka  [B*N1*HA];
__device__ float g_v   [B*N1*D];
__device__ int   g_nidx[B*N1*KNN];
__device__ float g_hpos [MROW*HP];
__device__ float g_hattn[MROW*HA];
__device__ float g_x   [B*N1*D];
__device__ float g_WkWa1[D*HA];
__device__ float g_WqWa1[D*HA];
__device__ float g_Wp2a [HP*HA];
__device__ float g_cvec [HA];
// [0:64) psum [64:128) psq [128:192) asum [192:256) asq
__device__ float g_stats[256];

// ================= tf32 mma helpers ===========================================
__device__ __forceinline__ uint32_t f2tf(float x) {
    uint32_t r; asm("cvt.rna.tf32.f32 %0, %1;" : "=r"(r) : "f"(x)); return r;
}
__device__ __forceinline__ void mma8(float* d, const uint32_t* a, const uint32_t* b) {
    asm volatile("mma.sync.aligned.m16n8k8.row.col.f32.tf32.tf32.f32 "
        "{%0,%1,%2,%3}, {%4,%5,%6,%7}, {%8,%9}, {%0,%1,%2,%3};"
        : "+f"(d[0]), "+f"(d[1]), "+f"(d[2]), "+f"(d[3])
        : "r"(a[0]), "r"(a[1]), "r"(a[2]), "r"(a[3]), "r"(b[0]), "r"(b[1]));
}

// ------ tf32x2 GEMM body: 128x128 tile, 512 threads, hi/lo planes, 3-mma ------
#define APITCH 36
#define BPITCH 136
#define TF32_SMEM_FLOATS (2*128*APITCH + 2*32*BPITCH)

__device__ __forceinline__ void gemm_tf32_body(
    const float* __restrict__ A, const float* __restrict__ W,
    const float* __restrict__ bias, const float* __restrict__ resid,
    float* __restrict__ C, int bx, int by, int N, int K)
{
    extern __shared__ float smext[];
    float* AHs = smext;
    float* ALs = AHs + 128*APITCH;
    float* BHs = ALs + 128*APITCH;
    float* BLs = BHs + 32*BPITCH;
    int tid = threadIdx.x;
    int row0 = by * 128, col0 = bx * 128;
    int warp = tid >> 5, lane = tid & 31;
    int mw = (warp & 3) * 32, nw = (warp >> 2) * 32;
    int g = lane >> 2, tg = lane & 3;
    float acc[8][4] = {};
    for (int k0 = 0; k0 < K; k0 += 32) {
#pragma unroll
        for (int i = 0; i < 2; i++) {
            int idx = tid + i*512;
            int r = idx >> 3, c4 = (idx & 7) * 4;
            float4 v = *(const float4*)&A[(size_t)(row0+r)*K + k0 + c4];
            float xs[4] = {v.x, v.y, v.z, v.w};
#pragma unroll
            for (int u = 0; u < 4; u++) {
                uint32_t hi = f2tf(xs[u]);
                AHs[r*APITCH + c4+u] = __uint_as_float(hi);
                ALs[r*APITCH + c4+u] = __uint_as_float(f2tf(xs[u] - __uint_as_float(hi)));
            }
        }
#pragma unroll
        for (int i = 0; i < 2; i++) {
            int idx = tid + i*512;
            int r = idx >> 5, c4 = (idx & 31) * 4;
            float4 v = *(const float4*)&W[(size_t)(k0+r)*N + col0 + c4];
            float xs[4] = {v.x, v.y, v.z, v.w};
#pragma unroll
            for (int u = 0; u < 4; u++) {
                uint32_t hi = f2tf(xs[u]);
                BHs[r*BPITCH + c4+u] = __uint_as_float(hi);
                BLs[r*BPITCH + c4+u] = __uint_as_float(f2tf(xs[u] - __uint_as_float(hi)));
            }
        }
        __syncthreads();
#pragma unroll
        for (int ks = 0; ks < 32; ks += 8) {
            uint32_t ah[2][4], al[2][4], bh[4][2], bl[4][2];
#pragma unroll
            for (int mi = 0; mi < 2; mi++) {
                int rb = mw + mi*16;
                ah[mi][0] = __float_as_uint(AHs[(rb+g  )*APITCH + ks+tg  ]);
                ah[mi][1] = __float_as_uint(AHs[(rb+g+8)*APITCH + ks+tg  ]);
                ah[mi][2] = __float_as_uint(AHs[(rb+g  )*APITCH + ks+tg+4]);
                ah[mi][3] = __float_as_uint(AHs[(rb+g+8)*APITCH + ks+tg+4]);
                al[mi][0] = __float_as_uint(ALs[(rb+g  )*APITCH + ks+tg  ]);
                al[mi][1] = __float_as_uint(ALs[(rb+g+8)*APITCH + ks+tg  ]);
                al[mi][2] = __float_as_uint(ALs[(rb+g  )*APITCH + ks+tg+4]);
                al[mi][3] = __float_as_uint(ALs[(rb+g+8)*APITCH + ks+tg+4]);
            }
#pragma unroll
            for (int ni = 0; ni < 4; ni++) {
                bh[ni][0] = __float_as_uint(BHs[(ks+tg  )*BPITCH + nw + ni*8 + g]);
                bh[ni][1] = __float_as_uint(BHs[(ks+tg+4)*BPITCH + nw + ni*8 + g]);
                bl[ni][0] = __float_as_uint(BLs[(ks+tg  )*BPITCH + nw + ni*8 + g]);
                bl[ni][1] = __float_as_uint(BLs[(ks+tg+4)*BPITCH + nw + ni*8 + g]);
            }
#pragma unroll
            for (int mi = 0; mi < 2; mi++)
#pragma unroll
                for (int ni = 0; ni < 4; ni++) {
                    mma8(acc[mi*4+ni], ah[mi], bh[ni]);
                    mma8(acc[mi*4+ni], ah[mi], bl[ni]);
                    mma8(acc[mi*4+ni], al[mi], bh[ni]);
                }
        }
        __syncthreads();
    }
#pragma unroll
    for (int mi = 0; mi < 2; mi++) {
#pragma unroll
        for (int ni = 0; ni < 4; ni++) {
            int c = col0 + nw + ni*8 + 2*tg;
            float b0 = bias ? bias[c]   : 0.f;
            float b1 = bias ? bias[c+1] : 0.f;
            size_t r1 = (size_t)(row0 + mw + mi*16 + g);
            size_t r2 = r1 + 8;
            float v00 = acc[mi*4+ni][0] + b0, v01 = acc[mi*4+ni][1] + b1;
            float v10 = acc[mi*4+ni][2] + b0, v11 = acc[mi*4+ni][3] + b1;
            if (resid) {
                v00 += resid[r1*N+c]; v01 += resid[r1*N+c+1];
                v10 += resid[r2*N+c]; v11 += resid[r2*N+c+1];
            }
            *(float2*)&C[r1*N + c] = make_float2(v00, v01);
            *(float2*)&C[r2*N + c] = make_float2(v10, v11);
        }
    }
}

// ---------------- combined post-GEMMs (z selects output head) ------------------
__global__ void __launch_bounds__(512)
gemm_post_kernel(const float* __restrict__ X,
                 const float* __restrict__ W1, const float* __restrict__ b1,
                 const float* __restrict__ resid1, float* __restrict__ out1,
                 const float* __restrict__ W2, const float* __restrict__ b2,
                 float* __restrict__ out2)
{
    if (blockIdx.z == 0)
        gemm_tf32_body(X, W1, b1, resid1, out1, blockIdx.x, blockIdx.y, D, D);
    else
        gemm_tf32_body(X, W2, b2, nullptr, out2, blockIdx.x, blockIdx.y, D, D);
}

// ---------------- FPS body: 512 threads, register-resident coords --------------
__device__ void fps_body(int b, const float* __restrict__ decpc,
                         const float* __restrict__ encpc)
{
    extern __shared__ float smext[];
    float* sx = smext;
    float* sy = smext + NC;
    float* sz = smext + 2*NC;
    __shared__ unsigned long long swk[2][16];

    int tid = threadIdx.x;
    int wid = tid >> 5, lid = tid & 31;

    for (int j = tid; j < N1; j += 512) {
        sx[j] = decpc[((size_t)b*N1 + j)*3 + 0];
        sy[j] = decpc[((size_t)b*N1 + j)*3 + 1];
        sz[j] = decpc[((size_t)b*N1 + j)*3 + 2];
        sx[N1+j] = encpc[((size_t)b*N2 + j)*3 + 0];
        sy[N1+j] = encpc[((size_t)b*N2 + j)*3 + 1];
        sz[N1+j] = encpc[((size_t)b*N2 + j)*3 + 2];
    }
    if (tid == 0) g_fidx[b*N1] = 0;
    int cur = 0;
    __syncthreads();

    float X[8], Y[8], Z[8], md[8];
#pragma unroll
    for (int t = 0; t < 8; t++) {
        int j = tid + t*512;
        X[t] = sx[j]; Y[t] = sy[j]; Z[t] = sz[j];
        md[t] = 1e10f;
    }

    for (int i = 1; i < N1; i++) {
        float lx = sx[cur], ly = sy[cur], lz = sz[cur];
        float bestv = -1.0f; int besti = 0x7fffffff;
#pragma unroll
        for (int t = 0; t < 8; t++) {
            float ddx = X[t]-lx, ddy = Y[t]-ly, ddz = Z[t]-lz;
            float d = ddx*ddx + ddy*ddy + ddz*ddz;
            float mm = fminf(md[t], d);
            md[t] = mm;
            if (mm > bestv) { bestv = mm; besti = tid + t*512; }
        }
        unsigned kb = __float_as_uint(bestv);
        kb = ((int)kb < 0) ? ~kb : (kb | 0x80000000u);
        unsigned mk;
        asm("redux.sync.max.u32 %0, %1, 0xffffffff;" : "=r"(mk) : "r"(kb));
        unsigned idxc = (kb == mk) ? (unsigned)besti : 0xffffffffu;
        unsigned mi;
        asm("redux.sync.min.u32 %0, %1, 0xffffffff;" : "=r"(mi) : "r"(idxc));
        int pb = i & 1;
        if (lid == 0)
            swk[pb][wid] = (((unsigned long long)mk) << 32) | (unsigned long long)(0xffffffffu - mi);
        __syncthreads();
        unsigned long long best = swk[pb][0];
#pragma unroll
        for (int w = 1; w < 16; w++) {
            unsigned long long o = swk[pb][w];
            best = (o > best) ? o : best;
        }
        cur = (int)(0xffffffffu - (unsigned)best);
        if (tid == 0) g_fidx[b*N1 + i] = cur;
    }
}

// ---------------- small 64-col GEMM body (weight precomputes), 512 thr --------
#define TBM 64
#define TBK 16
__device__ void gemm64_body(const float* __restrict__ A, const float* __restrict__ W,
                            float* __restrict__ C, int row0, int N, int K)
{
    __shared__ float As64[TBK][TBM];
    __shared__ float Bs64[TBK][64];
    int tid = threadIdx.x;
    for (int k0 = 0; k0 < K; k0 += TBK) {
#pragma unroll
        for (int u = 0; u < 2; u++) {
            int e = tid + u*512;
            int r = e >> 4, c = e & 15;
            As64[c][r] = A[(size_t)(row0 + r)*K + k0 + c];
            int r2 = e >> 6, c2 = e & 63;
            Bs64[r2][c2] = W[(size_t)(k0 + r2)*N + c2];
        }
        __syncthreads();
        if (tid < 256) {
            int tx = tid & 15, ty = tid >> 4;
            float acc[4][4] = {};
#pragma unroll
            for (int kk = 0; kk < TBK; kk++) {
                float a[4], bb[4];
#pragma unroll
                for (int i = 0; i < 4; i++) a[i] = As64[kk][ty*4+i];
#pragma unroll
                for (int j = 0; j < 4; j++) bb[j] = Bs64[kk][tx*4+j];
#pragma unroll
                for (int i = 0; i < 4; i++)
#pragma unroll
                    for (int j = 0; j < 4; j++)
                        acc[i][j] += a[i]*bb[j];
            }
#pragma unroll
            for (int i = 0; i < 4; i++)
#pragma unroll
                for (int j = 0; j < 4; j++) {
                    size_t off = (size_t)(row0 + ty*4 + i)*N + tx*4 + j;
                    if (k0 == 0) C[off] = acc[i][j];
                    else         C[off] += acc[i][j];
                }
        }
        __syncthreads();
    }
}

// ---------------- cvec body: (bk - bq + bp2) @ Wa1 + ba1, 512 thr --------------
__device__ void cvec_body(const float* __restrict__ bk, const float* __restrict__ bq,
                          const float* __restrict__ bp2, const float* __restrict__ Wa1,
                          const float* __restrict__ ba1)
{
    __shared__ float shc[512];
    int c = threadIdx.x & 63;
    int part = threadIdx.x >> 6;     // 0..7
    float s = 0.f;
    for (int i = part*32; i < part*32 + 32; i++)
        s += (bk[i] - bq[i] + bp2[i]) * Wa1[(size_t)i*HA + c];
    shc[threadIdx.x] = s;
    __syncthreads();
    if (part == 0) {
        float t = ba1[c];
#pragma unroll
        for (int p = 0; p < 8; p++) t += shc[p*64 + c];
        g_cvec[c] = t;
    }
}

// ---------------- phase-1 mega-kernel -----------------------------------------
__global__ void __launch_bounds__(512)
phase1_kernel(const float* __restrict__ dec_pc, const float* __restrict__ enc_pc,
              const float* __restrict__ dec_x,  const float* __restrict__ enc_x,
              const float* __restrict__ W_pre1, const float* __restrict__ b_pre1,
              const float* __restrict__ W_pre2, const float* __restrict__ b_pre2,
              const float* __restrict__ Wk, const float* __restrict__ Wq,
              const float* __restrict__ Wa1, const float* __restrict__ Wp2,
              const float* __restrict__ bk, const float* __restrict__ bq,
              const float* __restrict__ bp2, const float* __restrict__ ba1)
{
    int bid = blockIdx.x;
    if (bid < 4) {
        fps_body(bid, dec_pc, enc_pc);
    } else if (bid < 132) {
        int t = bid - 4;
        gemm_tf32_body(dec_x, W_pre1, b_pre1, nullptr, g_dx, t & 1, t >> 1, D, D);
    } else if (bid < 260) {
        int t = bid - 132;
        gemm_tf32_body(enc_x, W_pre2, b_pre2, nullptr, g_ex, t & 1, t >> 1, D, D);
    } else if (bid < 264) {
        gemm64_body(Wk, Wa1, g_WkWa1, (bid-260)*64, HA, D);
    } else if (bid < 268) {
        gemm64_body(Wq, Wa1, g_WqWa1, (bid-264)*64, HA, D);
    } else if (bid == 268) {
        gemm64_body(Wp2, Wa1, g_Wp2a, 0, HA, D);
    } else if (bid == 269) {
        cvec_body(bk, bq, bp2, Wa1, ba1);
    } else {
        if (threadIdx.x < 256) g_stats[threadIdx.x] = 0.0f;
    }
}

// ---------------- gather sampled features + coords ----------------------------
__global__ void gather_kernel(const float* __restrict__ decpc,
                              const float* __restrict__ encpc)
{
    int row = blockIdx.x*4 + (threadIdx.x >> 6);
    int c4  = (threadIdx.x & 63) * 4;
    int b = row >> 11;
    int j = g_fidx[row];
    const float* src = (j < N1) ? &g_dx[((size_t)b*N1 + j)*D]
                                : &g_ex[((size_t)b*N2 + (j - N1))*D];
    *(float4*)&g_sx[(size_t)row*D + c4] = *(const float4*)&src[c4];
    if ((threadIdx.x & 63) < 3) {
        int cc = threadIdx.x & 63;
        const float* ps = (j < N1) ? &decpc[((size_t)b*N1 + j)*3]
                                   : &encpc[((size_t)b*N2 + (j - N1))*3];
        g_spc[(size_t)row*3 + cc] = ps[cc];
    }
}

// ---------------- N=64 GEMM body for 512 threads (qa/ka) -----------------------
__device__ void n64_body_512(const float* __restrict__ A, const float* __restrict__ W,
                             float* __restrict__ C, int row0)
{
    __shared__ float Asq[16][132];
    __shared__ float Bsq[16][64];
    int tid = threadIdx.x;
    int tx = tid & 15, ty = tid >> 4;          // ty 0..31
    float acc[4][4] = {};
    for (int k0 = 0; k0 < D; k0 += 16) {
        {
            int r = tid >> 2, kq = (tid & 3) * 4;
            float4 va = *(const float4*)&A[(size_t)(row0 + r)*D + k0 + kq];
            Asq[kq+0][r] = va.x; Asq[kq+1][r] = va.y;
            Asq[kq+2][r] = va.z; Asq[kq+3][r] = va.w;
        }
        if (tid < 256) {
            int r = tid >> 4, cq = (tid & 15) * 4;
            *(float4*)&Bsq[r][cq] = *(const float4*)&W[(size_t)(k0 + r)*HA + cq];
        }
        __syncthreads();
#pragma unroll
        for (int kk = 0; kk < 16; kk++) {
            float a[4], bb[4];
#pragma unroll
            for (int i = 0; i < 4; i++) a[i] = Asq[kk][ty*4+i];
#pragma unroll
            for (int j = 0; j < 4; j++) bb[j] = Bsq[kk][tx*4+j];
#pragma unroll
            for (int i = 0; i < 4; i++)
#pragma unroll
                for (int j = 0; j < 4; j++)
                    acc[i][j] += a[i]*bb[j];
        }
        __syncthreads();
    }
#pragma unroll
    for (int i = 0; i < 4; i++)
#pragma unroll
        for (int j = 0; j < 4; j++)
            C[(size_t)(row0 + ty*4 + i)*HA + tx*4 + j] = acc[i][j];
}

// ---------------- phase-2 mega-kernel: KNN + qa/ka + v -------------------------
__global__ void __launch_bounds__(512)
phase2_kernel(const float* __restrict__ decpc,
              const float* __restrict__ Wv, const float* __restrict__ bv)
{
    int bid = blockIdx.x;
    if (bid < 32) {
        extern __shared__ float s2[];
        float* px = s2; float* py = px + 2048; float* pz = py + 2048; float* s2s = pz + 2048;
        unsigned long long* buf = (unsigned long long*)(s2 + 8192);
        int tid = threadIdx.x;
        int b = bid >> 3, qb = bid & 7;
        for (int m = tid; m < 2048; m += 512) {
            float x = g_spc[((size_t)b*N1 + m)*3 + 0];
            float y = g_spc[((size_t)b*N1 + m)*3 + 1];
            float z = g_spc[((size_t)b*N1 + m)*3 + 2];
            px[m] = x; py[m] = y; pz[m] = z;
            s2s[m] = x*x + y*y + z*z;
        }
        __syncthreads();
        int qi = tid & 255, h = tid >> 8;
        int q = qb*256 + qi;
        float qx = decpc[((size_t)b*N1 + q)*3 + 0];
        float qy = decpc[((size_t)b*N1 + q)*3 + 1];
        float qz = decpc[((size_t)b*N1 + q)*3 + 2];
        float s1 = qx*qx + qy*qy + qz*qz;
        float bd[KNN]; int bi[KNN];
#pragma unroll
        for (int t = 0; t < KNN; t++) { bd[t] = 1e30f; bi[t] = 0; }
        int mbase = h * 1024;
        for (int mm = 0; mm < 1024; mm++) {
            int m = mbase + mm;
            float d = s1 + s2s[m] - 2.0f*(qx*px[m] + qy*py[m] + qz*pz[m]);
            if (d < bd[KNN-1]) {
                bd[KNN-1] = d; bi[KNN-1] = m;
#pragma unroll
                for (int t = KNN-1; t > 0; t--) {
                    if (bd[t] < bd[t-1]) {
                        float td = bd[t]; bd[t] = bd[t-1]; bd[t-1] = td;
                        int   ti = bi[t]; bi[t] = bi[t-1]; bi[t-1] = ti;
                    }
                }
            }
        }
#pragma unroll
        for (int t = 0; t < KNN; t++) {
            unsigned u = __float_as_uint(bd[t]);
            u = ((int)u < 0) ? ~u : (u | 0x80000000u);
            buf[(size_t)tid*KNN + t] = (((unsigned long long)u) << 32) | (unsigned)bi[t];
        }
        __syncthreads();
        if (h == 0) {
            const unsigned long long* A_ = &buf[(size_t)qi*KNN];
            const unsigned long long* B_ = &buf[(size_t)(qi+256)*KNN];
            int* outp = &g_nidx[((size_t)b*N1 + q)*KNN];
            int ia = 0, ib = 0;
#pragma unroll
            for (int o = 0; o < KNN; o++) {
                unsigned long long av = A_[ia], bv_ = B_[ib];
                if ((av >> 32) <= (bv_ >> 32)) { outp[o] = (int)(unsigned)av; ia++; }
                else                           { outp[o] = (int)(unsigned)bv_; ib++; }
            }
        }
    } else if (bid < 160) {
        int t = bid - 32;
        int sel = t >> 6, tile = t & 63;
        n64_body_512(sel ? g_sx : g_dx, sel ? g_WkWa1 : g_WqWa1,
                     sel ? g_ka : g_qa, tile*128);
    } else {
        int t = bid - 160;
        gemm_tf32_body(g_sx, Wv, bv, nullptr, g_v, t & 1, t >> 1, D, D);
    }
}

// ---------------- hpos + fused BN stats ----------------------------------------
// grid 512 blocks x 256 threads; each block 256 rows
__global__ void __launch_bounds__(256)
hpos_kernel(const float* __restrict__ decpc,
            const float* __restrict__ Wp1,
            const float* __restrict__ bp1)
{
    int tid = threadIdx.x;
    int c = tid & 63;
    int rg = tid >> 6;
    float w0 = Wp1[c], w1 = Wp1[64+c], w2 = Wp1[128+c], bb = bp1[c];
    float s = 0.f, s2 = 0.f;
    int base = blockIdx.x * 256;
    for (int it = 0; it < 64; it++) {
        int m = base + it*4 + rg;
        int b = m >> 15;
        int n = (m >> 4) & 2047;
        int j = g_nidx[m];
        const float* pp = &g_spc[((size_t)b*N1 + j)*3];
        const float* qq = &decpc[((size_t)b*N1 + n)*3];
        float p0 = pp[0]-qq[0], p1 = pp[1]-qq[1], p2 = pp[2]-qq[2];
        float h = p0*w0 + p1*w1 + p2*w2 + bb;
        g_hpos[(size_t)m*HP + c] = h;
        s += h; s2 += h*h;
    }
    __shared__ float sh[256], sh2[256];
    sh[tid] = s; sh2[tid] = s2;
    __syncthreads();
    if (rg == 0) {
        atomicAdd(&g_stats[c],    sh[c] + sh[64+c] + sh[128+c] + sh[192+c]);
        atomicAdd(&g_stats[64+c], sh2[c] + sh2[64+c] + sh2[128+c] + sh2[192+c]);
    }
}

// ---- hattn = relu(bn_pos(hp)) @ Wp2a + ka[gather] - qa + cvec + stats --------
__global__ void __launch_bounds__(256)
hattn_kernel(const float* __restrict__ gp, const float* __restrict__ betap)
{
    __shared__ float Aw[64][65];
    __shared__ float Bw[64*64];
    __shared__ float psc[64], psh[64];
    __shared__ float rs[16][64], rs2[16][64];
    int tid = threadIdx.x;
    int m0 = blockIdx.x * 64;
    if (tid < 64) {
        float mean = g_stats[tid] * INV_MROW;
        float var  = g_stats[64+tid] * INV_MROW - mean*mean;
        float sc = gp[tid]*rsqrtf(var + 1e-5f);
        psc[tid] = sc;
        psh[tid] = betap[tid] - mean*sc;
    }
    __syncthreads();
#pragma unroll
    for (int i = 0; i < 16; i++) {
        int idx = tid + i*256;
        int r = idx >> 6, k = idx & 63;
        float h = g_hpos[(size_t)(m0+r)*64 + k];
        Aw[r][k] = fmaxf(h*psc[k] + psh[k], 0.0f);
        Bw[idx] = g_Wp2a[idx];
    }
    __syncthreads();
    int tx = tid & 15, ty = tid >> 4;
    float acc[4][4] = {};
#pragma unroll 4
    for (int kk = 0; kk < 64; kk++) {
        float a[4], bb[4];
#pragma unroll
        for (int i = 0; i < 4; i++) a[i] = Aw[ty*4+i][kk];
#pragma unroll
        for (int j = 0; j < 4; j++) bb[j] = Bw[kk*64 + tx*4 + j];
#pragma unroll
        for (int i = 0; i < 4; i++)
#pragma unroll
            for (int j = 0; j < 4; j++)
                acc[i][j] += a[i]*bb[j];
    }
    float ps[4] = {0,0,0,0}, ps2[4] = {0,0,0,0};
#pragma unroll
    for (int i = 0; i < 4; i++) {
        int m = m0 + ty*4 + i;
        int b = m >> 15;
        int n = (m >> 4) & 2047;
        int jj = g_nidx[m];
        const float* kar = &g_ka[(((size_t)b<<11) + jj)*HA];
        const float* qar = &g_qa[(((size_t)b<<11) + n )*HA];
#pragma unroll
        for (int j = 0; j < 4; j++) {
            int c = tx*4 + j;
            float v = acc[i][j] + kar[c] - qar[c] + g_cvec[c];
            g_hattn[(size_t)m*HA + c] = v;
            ps[j] += v; ps2[j] += v*v;
        }
    }
#pragma unroll
    for (int j = 0; j < 4; j++) {
        rs[ty][tx*4+j] = ps[j];
        rs2[ty][tx*4+j] = ps2[j];
    }
    __syncthreads();
    if (tid < 64) {
        float s = 0.f, s2 = 0.f;
#pragma unroll
        for (int t = 0; t < 16; t++) { s += rs[t][tid]; s2 += rs2[t][tid]; }
        atomicAdd(&g_stats[128+tid], s);
        atomicAdd(&g_stats[192+tid], s2);
    }
}

// ---- fused: attn/pos GEMMs via tf32x2 mma + softmax(K) + agg -> g_x ----------
// grid 2048; block handles 64 rows x 256 cols (two 128-col halves, A reused)
__global__ void __launch_bounds__(256)
attnout_kernel(const float* __restrict__ Wa2,
               const float* __restrict__ ba2,
               const float* __restrict__ Wp2,
               const float* __restrict__ bp2,
               const float* __restrict__ gp, const float* __restrict__ betap,
               const float* __restrict__ ga, const float* __restrict__ betaa)
{
    extern __shared__ float sm[];
    float* Ahr    = sm;                 // [64][68]
    float* Apr    = Ahr + 64*68;        // [64][68]
    float* attn_s = Apr + 64*68;        // [64][132]
    float* pos_s  = attn_s + 64*132;    // [64][132]
    float* Bh     = pos_s + 64*132;     // [16][136]
    float* Bl     = Bh + 16*136;        // [16][136]
    float* scbuf  = Bl + 16*136;        // psc,psh,asc,ash [4][64]
    int*   sj     = (int*)(scbuf + 256);// [64]

    int tid = threadIdx.x;
    int m0 = blockIdx.x * 64;
    int warp = tid >> 5, lane = tid & 31;
    int mw = (warp & 3) * 16, nw = (warp >> 2) * 64;
    int g = lane >> 2, tg = lane & 3;

    if (tid < 64) {
        float mean = g_stats[tid] * INV_MROW;
        float var  = g_stats[64+tid] * INV_MROW - mean*mean;
        float sc = gp[tid]*rsqrtf(var + 1e-5f);
        scbuf[tid] = sc;
        scbuf[64+tid] = betap[tid] - mean*sc;
        mean = g_stats[128+tid] * INV_MROW;
        var  = g_stats[192+tid] * INV_MROW - mean*mean;
        sc = ga[tid]*rsqrtf(var + 1e-5f);
        scbuf[128+tid] = sc;
        scbuf[192+tid] = betaa[tid] - mean*sc;
        sj[tid] = g_nidx[m0 + tid];
    }
    __syncthreads();

#pragma unroll
    for (int i = 0; i < 16; i++) {
        int idx = tid + i*256;
        int r = idx >> 6, k = idx & 63;
        float ha = g_hattn[(size_t)(m0+r)*64 + k];
        Ahr[r*68 + k] = fmaxf(ha*scbuf[128+k] + scbuf[192+k], 0.0f);
        float hp = g_hpos[(size_t)(m0+r)*64 + k];
        Apr[r*68 + k] = fmaxf(hp*scbuf[k] + scbuf[64+k], 0.0f);
    }

    for (int half = 0; half < 2; half++) {
        int c0 = half * 128;
#pragma unroll
        for (int pass = 0; pass < 2; pass++) {
            const float* Wsrc = pass ? Wp2 : Wa2;
            const float* bsrc = pass ? bp2 : ba2;
            const float* Asm  = pass ? Apr : Ahr;
            float* Out = pass ? pos_s : attn_s;
            float acc[8][4] = {};
            for (int k0 = 0; k0 < 64; k0 += 16) {
                __syncthreads();
#pragma unroll
                for (int i = 0; i < 8; i++) {
                    int idx = tid + i*256;
                    int r = idx >> 7, c = idx & 127;
                    float x = Wsrc[(size_t)(k0+r)*D + c0 + c];
                    uint32_t hi = f2tf(x);
                    Bh[r*136 + c] = __uint_as_float(hi);
                    Bl[r*136 + c] = __uint_as_float(f2tf(x - __uint_as_float(hi)));
                }
                __syncthreads();
#pragma unroll
                for (int ks = 0; ks < 16; ks += 8) {
                    uint32_t ah[4], al[4];
                    {
                        float x0 = Asm[(mw+g  )*68 + k0+ks+tg  ];
                        float x1 = Asm[(mw+g+8)*68 + k0+ks+tg  ];
                        float x2 = Asm[(mw+g  )*68 + k0+ks+tg+4];
                        float x3 = Asm[(mw+g+8)*68 + k0+ks+tg+4];
                        ah[0] = f2tf(x0); al[0] = f2tf(x0 - __uint_as_float(ah[0]));
                        ah[1] = f2tf(x1); al[1] = f2tf(x1 - __uint_as_float(ah[1]));
                        ah[2] = f2tf(x2); al[2] = f2tf(x2 - __uint_as_float(ah[2]));
                        ah[3] = f2tf(x3); al[3] = f2tf(x3 - __uint_as_float(ah[3]));
                    }
#pragma unroll
                    for (int ni = 0; ni < 8; ni++) {
                        uint32_t bhf[2], blf[2];
                        bhf[0] = __float_as_uint(Bh[(ks+tg  )*136 + nw + ni*8 + g]);
                        bhf[1] = __float_as_uint(Bh[(ks+tg+4)*136 + nw + ni*8 + g]);
                        blf[0] = __float_as_uint(Bl[(ks+tg  )*136 + nw + ni*8 + g]);
                        blf[1] = __float_as_uint(Bl[(ks+tg+4)*136 + nw + ni*8 + g]);
                        mma8(acc[ni], ah, bhf);
                        mma8(acc[ni], ah, blf);
                        mma8(acc[ni], al, bhf);
                    }
                }
            }
#pragma unroll
            for (int ni = 0; ni < 8; ni++) {
                int c = nw + ni*8 + 2*tg;
                float b0 = bsrc[c0 + c], b1 = bsrc[c0 + c + 1];
                Out[(mw+g  )*132 + c]     = acc[ni][0] + b0;
                Out[(mw+g  )*132 + c + 1] = acc[ni][1] + b1;
                Out[(mw+g+8)*132 + c]     = acc[ni][2] + b0;
                Out[(mw+g+8)*132 + c + 1] = acc[ni][3] + b1;
            }
        }
        __syncthreads();

        // softmax over 16 neighbors + aggregation for this 128-col half
#pragma unroll
        for (int e = tid; e < 512; e += 256) {
            int q = e >> 7;            // 0..3
            int c = e & 127;
            int mrow = q*16;
            float mx = -1e30f;
#pragma unroll
            for (int k = 0; k < KNN; k++)
                mx = fmaxf(mx, attn_s[(mrow+k)*132 + c]);
            float w[KNN]; float s = 0.f;
#pragma unroll
            for (int k = 0; k < KNN; k++) {
                w[k] = __expf(attn_s[(mrow+k)*132 + c] - mx);
                s += w[k];
            }
            float inv = 1.0f / s;
            int qg = (m0 >> 4) + q;
            int b = qg >> 11;
            float x = 0.f;
#pragma unroll
            for (int k = 0; k < KNN; k++) {
                int j = sj[mrow + k];
                float vv = g_v[(((size_t)b<<11) + j)*D + c0 + c] + pos_s[(mrow+k)*132 + c];
                x += vv * w[k];
            }
            g_x[(size_t)qg*D + c0 + c] = x * inv;
        }
        __syncthreads();
    }
}

// =================================================================================
extern "C" void kernel_launch(void* const* d_in, const int* in_sizes, int n_in,
                              void* d_out, int out_size)
{
    const float* dec_x   = (const float*)d_in[0];
    const float* dec_pc  = (const float*)d_in[1];
    const float* enc_x   = (const float*)d_in[2];
    const float* enc_pc  = (const float*)d_in[3];
    const float* W_pre1  = (const float*)d_in[4];
    const float* b_pre1  = (const float*)d_in[5];
    const float* W_pre2  = (const float*)d_in[6];
    const float* b_pre2  = (const float*)d_in[7];
    const float* Wq      = (const float*)d_in[8];
    const float* bq      = (const float*)d_in[9];
    const float* Wk      = (const float*)d_in[10];
    const float* bk      = (const float*)d_in[11];
    const float* Wv      = (const float*)d_in[12];
    const float* bv      = (const float*)d_in[13];
    const float* Wp1     = (const float*)d_in[14];
    const float* bp1     = (const float*)d_in[15];
    const float* gp      = (const float*)d_in[16];
    const float* betap   = (const float*)d_in[17];
    const float* Wp2     = (const float*)d_in[18];
    const float* bp2     = (const float*)d_in[19];
    const float* Wa1     = (const float*)d_in[20];
    const float* ba1     = (const float*)d_in[21];
    const float* ga      = (const float*)d_in[22];
    const float* betaa   = (const float*)d_in[23];
    const float* Wa2     = (const float*)d_in[24];
    const float* ba2     = (const float*)d_in[25];
    const float* W_post1 = (const float*)d_in[26];
    const float* b_post1 = (const float*)d_in[27];
    const float* W_post2 = (const float*)d_in[28];
    const float* b_post2 = (const float*)d_in[29];
    float* out = (float*)d_out;

    float *p_x;
    cudaGetSymbolAddress((void**)&p_x, g_x);

    const int M8 = B*N1;                         // 8192
    const int PH1_SMEM  = TF32_SMEM_FLOATS*4;                 // 71680 (>= FPS 49152)
    const int PH2_SMEM  = 8192*4 + 512*KNN*8;                 // 98304
    const int ATTN_SMEM = (64*68*2 + 64*132*2 + 16*136*2 + 256)*4 + 64*4;
    const int POST_SMEM = TF32_SMEM_FLOATS*4;

    // 1) phase-1: FPS || pre-projections || weight precomputes || cvec || zero
    cudaFuncSetAttribute(phase1_kernel, cudaFuncAttributeMaxDynamicSharedMemorySize, PH1_SMEM);
    phase1_kernel<<<271, 512, PH1_SMEM>>>(dec_pc, enc_pc, dec_x, enc_x,
                                          W_pre1, b_pre1, W_pre2, b_pre2,
                                          Wk, Wq, Wa1, Wp2, bk, bq, bp2, ba1);

    // 2) gather sampled features + coords
    gather_kernel<<<M8/4, 256>>>(dec_pc, enc_pc);

    // 3) phase-2: KNN || qa/ka || v
    cudaFuncSetAttribute(phase2_kernel, cudaFuncAttributeMaxDynamicSharedMemorySize, PH2_SMEM);
    phase2_kernel<<<288, 512, PH2_SMEM>>>(dec_pc, Wv, bv);

    // 4) hpos + fused pos-BN stats
    hpos_kernel<<<512, 256>>>(dec_pc, Wp1, bp1);

    // 5) hattn (inline pos-BN finalize) + fused attn-BN stats
    hattn_kernel<<<MROW/64, 256>>>(gp, betap);

    // 6) fused attn/pos mma GEMMs + softmax + aggregation (inline BN finalize)
    cudaFuncSetAttribute(attnout_kernel, cudaFuncAttributeMaxDynamicSharedMemorySize, ATTN_SMEM);
    attnout_kernel<<<MROW/64, 256, ATTN_SMEM>>>(Wa2, ba2, Wp2, bp2, gp, betap, ga, betaa);

    // 7) outputs (both post GEMMs in one launch)
    float* out1 = out;                                   // [B,N1,256]
    float* opc1 = out + (size_t)M8*D;                    // [B,N1,3]
    float* out2 = opc1 + (size_t)M8*3;                   // [B,N1,256]
    float* opc2 = out2 + (size_t)M8*D;                   // [B,N2,3]
    cudaFuncSetAttribute(gemm_post_kernel, cudaFuncAttributeMaxDynamicSharedMemorySize, POST_SMEM);
    gemm_post_kernel<<<dim3(2, M8/128, 2), 512, POST_SMEM>>>(p_x, W_post1, b_post1, dec_x, out1,
                                                             W_post2, b_post2, out2);
    cudaMemcpyAsync(opc1, dec_pc, (size_t)M8*3*sizeof(float), cudaMemcpyDeviceToDevice);
    cudaMemcpyAsync(opc2, enc_pc, (size_t)B*N2*3*sizeof(float), cudaMemcpyDeviceToDevice);
}